// round 2
// baseline (speedup 1.0000x reference)
#include <cuda_runtime.h>
#include <cstdint>

#define T_CAP 64
#define BATCH 256
#define DEC   1024
#define HID   1024
#define ATTN  128

// ---------------- scratch (static device memory; no allocations) ----------------
__device__ float g_Uv[BATCH * T_CAP * ATTN];   // 8 MB  : U(feats)+b_attn, [b][t][a]
__device__ float g_h[2][BATCH * HID];          // double-buffered hidden state
__device__ float g_c[BATCH * HID];             // cell state (uniquely owned per (b,n))
__device__ float g_Wh[BATCH * ATTN];           // h @ W_attn^T per step
__device__ float g_p[BATCH * T_CAP];           // softmax weights per step
__device__ float g_ctx[BATCH * DEC];           // attention context per step

// ---------------- helpers ----------------
__device__ __forceinline__ uint32_t f2tf(float f) {
    uint32_t u;
    asm("cvt.rna.tf32.f32 %0, %1;" : "=r"(u) : "f"(f));
    return u;
}

__device__ __forceinline__ void mma8(float* c, const uint32_t* a, const uint32_t* b) {
    asm volatile(
        "mma.sync.aligned.m16n8k8.row.col.f32.tf32.tf32.f32 "
        "{%0,%1,%2,%3}, {%4,%5,%6,%7}, {%8,%9}, {%0,%1,%2,%3};\n"
        : "+f"(c[0]), "+f"(c[1]), "+f"(c[2]), "+f"(c[3])
        : "r"(a[0]), "r"(a[1]), "r"(a[2]), "r"(a[3]),
          "r"(b[0]), "r"(b[1]));
}

__device__ __forceinline__ void cp16(float* s, const float* g) {
    uint32_t sa = (uint32_t)__cvta_generic_to_shared(s);
    asm volatile("cp.async.ca.shared.global [%0], [%1], 16;\n" :: "r"(sa), "l"(g));
}
#define CP_COMMIT() asm volatile("cp.async.commit_group;\n" ::)
#define CP_WAIT2()  asm volatile("cp.async.wait_group 2;\n" ::)
#define CP_WAIT1()  asm volatile("cp.async.wait_group 1;\n" ::)
#define CP_WAIT0()  asm volatile("cp.async.wait_group 0;\n" ::)

__device__ __forceinline__ float sigf(float x) { return 1.0f / (1.0f + __expf(-x)); }
__device__ __forceinline__ float tanh_fast(float x) {
    // 1 - 2/(e^{2x}+1); stable at both tails with __expf
    return __fdividef(2.0f, 1.0f + __expf(-2.0f * x)) - 1.0f;
}

// ---------------- init: zero h0, c ----------------
__global__ void init_kernel() {
    int i = blockIdx.x * blockDim.x + threadIdx.x;
    if (i < BATCH * HID) {
        g_h[0][i] = 0.0f;
        g_c[i]    = 0.0f;
    }
}

// ---------------- Uv = feats @ U_attn^T + b_attn  (tf32 mma, one-time) ----------------
// M = B*T_CAP = 16384 (r = b*64 + t), N = ATTN = 128, K = 1024
__global__ __launch_bounds__(256) void uv_kernel(
    const float* __restrict__ dh, const float* __restrict__ U_attn,
    const float* __restrict__ b_attn)
{
    __shared__ __align__(16) float As[2][128][20];
    __shared__ __align__(16) float Bs[2][64][20];

    const int tid = threadIdx.x;
    const int m0 = blockIdx.x * 128;
    const int n0 = blockIdx.y * 64;

    const int am = tid >> 1;
    const int ak = (tid & 1) * 8;
    const int bj = tid >> 2;
    const int bk = (tid & 3) * 4;

    const int r = m0 + am;
    const long abase = ((long)((r & 63) * 256 + (r >> 6))) * 1024;  // feats row base
    const long bbase = (long)(n0 + bj) * 1024;

    const int warp = tid >> 5, lane = tid & 31;
    const int wm = (warp >> 2) * 64;
    const int wn = (warp & 3) * 16;
    const int lr = lane >> 2;
    const int lc = lane & 3;

    float acc[4][2][4];
#pragma unroll
    for (int i = 0; i < 4; i++)
#pragma unroll
        for (int j = 0; j < 2; j++)
#pragma unroll
            for (int k = 0; k < 4; k++) acc[i][j][k] = 0.0f;

    const int NS = 1024 / 16;

    {
        cp16(&As[0][am][ak],     dh + abase + 0 + ak);
        cp16(&As[0][am][ak + 4], dh + abase + 0 + ak + 4);
        cp16(&Bs[0][bj][bk],     U_attn + bbase + 0 + bk);
        CP_COMMIT();
    }

    for (int s = 0; s < NS; s++) {
        if (s + 1 < NS) {
            int buf = (s + 1) & 1, k0 = (s + 1) * 16;
            cp16(&As[buf][am][ak],     dh + abase + k0 + ak);
            cp16(&As[buf][am][ak + 4], dh + abase + k0 + ak + 4);
            cp16(&Bs[buf][bj][bk],     U_attn + bbase + k0 + bk);
            CP_COMMIT();
            CP_WAIT1();
        } else {
            CP_WAIT0();
        }
        __syncthreads();
        const int buf = s & 1;
#pragma unroll
        for (int kk = 0; kk < 16; kk += 8) {
            uint32_t af[4][4], bf[2][2];
#pragma unroll
            for (int fm = 0; fm < 4; fm++) {
                int rr = wm + fm * 16 + lr;
                af[fm][0] = f2tf(As[buf][rr][kk + lc]);
                af[fm][1] = f2tf(As[buf][rr + 8][kk + lc]);
                af[fm][2] = f2tf(As[buf][rr][kk + lc + 4]);
                af[fm][3] = f2tf(As[buf][rr + 8][kk + lc + 4]);
            }
#pragma unroll
            for (int fn = 0; fn < 2; fn++) {
                int jc = wn + fn * 8 + lr;
                bf[fn][0] = f2tf(Bs[buf][jc][kk + lc]);
                bf[fn][1] = f2tf(Bs[buf][jc][kk + lc + 4]);
            }
#pragma unroll
            for (int fm = 0; fm < 4; fm++)
#pragma unroll
                for (int fn = 0; fn < 2; fn++) mma8(acc[fm][fn], af[fm], bf[fn]);
        }
        __syncthreads();
    }

#pragma unroll
    for (int fm = 0; fm < 4; fm++) {
#pragma unroll
        for (int fn = 0; fn < 2; fn++) {
            int rr = m0 + wm + fm * 16 + lr;
            int a  = n0 + wn + fn * 8 + 2 * lc;
            float ba0 = b_attn[a], ba1 = b_attn[a + 1];
            float2 v0 = make_float2(acc[fm][fn][0] + ba0, acc[fm][fn][1] + ba1);
            float2 v1 = make_float2(acc[fm][fn][2] + ba0, acc[fm][fn][3] + ba1);
            *(float2*)&g_Uv[rr * ATTN + a]       = v0;
            *(float2*)&g_Uv[(rr + 8) * ATTN + a] = v1;
        }
    }
}

// ---------------- Wh = h @ W_attn^T (SIMT; 256x128x1024, tiny) ----------------
__global__ __launch_bounds__(256) void wh_kernel(const float* __restrict__ W_attn, int cur)
{
    __shared__ float hs[32][33];
    __shared__ float ws[16][33];
    const float* h = g_h[cur];
    const int tid = threadIdx.x;
    const int m0 = blockIdx.x * 32, a0 = blockIdx.y * 16;
    const int mi = tid >> 4, ai = tid & 15;
    float acc0 = 0.0f, acc1 = 0.0f;

    for (int k0 = 0; k0 < 1024; k0 += 32) {
        int hr = tid >> 3, hc = (tid & 7) * 4;
        float4 hv = *(const float4*)&h[(m0 + hr) * 1024 + k0 + hc];
        hs[hr][hc] = hv.x; hs[hr][hc + 1] = hv.y; hs[hr][hc + 2] = hv.z; hs[hr][hc + 3] = hv.w;
        int wr = tid >> 4, wc = (tid & 15) * 2;
        float2 wv = *(const float2*)&W_attn[(a0 + wr) * 1024 + k0 + wc];
        ws[wr][wc] = wv.x; ws[wr][wc + 1] = wv.y;
        __syncthreads();
#pragma unroll
        for (int kk = 0; kk < 32; kk++) {
            float w = ws[ai][kk];
            acc0 += hs[mi][kk] * w;
            acc1 += hs[mi + 16][kk] * w;
        }
        __syncthreads();
    }
    g_Wh[(m0 + mi) * ATTN + a0 + ai]      = acc0;
    g_Wh[(m0 + mi + 16) * ATTN + a0 + ai] = acc1;
}

// ---------------- energies + masked softmax -> g_p ----------------
// one block per batch row b; 128 threads (4 warps)
__global__ __launch_bounds__(128) void esoft_kernel(
    const int* __restrict__ caps, const float* __restrict__ w_attn)
{
    const int b = blockIdx.x, tid = threadIdx.x;
    const int warp = tid >> 5, lane = tid & 31;
    __shared__ float wh_s[ATTN], wa_s[ATTN], e_s[T_CAP];

    wh_s[tid] = g_Wh[b * ATTN + tid];
    wa_s[tid] = w_attn[tid];
    __syncthreads();

    for (int t = warp; t < T_CAP; t += 4) {
        const float* uv = g_Uv + (b * T_CAP + t) * ATTN;
        float s = 0.0f;
#pragma unroll
        for (int a = lane; a < ATTN; a += 32)
            s += wa_s[a] * tanh_fast(wh_s[a] + uv[a]);
#pragma unroll
        for (int off = 16; off; off >>= 1) s += __shfl_xor_sync(0xffffffffu, s, off);
        if (lane == 0) {
            int cp = caps[t * BATCH + b];
            e_s[t] = (cp != 0 && cp != 2) ? s : -1e30f;
        }
    }
    __syncthreads();

    if (warp == 0) {
        float e0 = e_s[lane], e1 = e_s[lane + 32];
        float mx = fmaxf(e0, e1);
#pragma unroll
        for (int off = 16; off; off >>= 1) mx = fmaxf(mx, __shfl_xor_sync(0xffffffffu, mx, off));
        float x0 = __expf(e0 - mx), x1 = __expf(e1 - mx);
        float sm = x0 + x1;
#pragma unroll
        for (int off = 16; off; off >>= 1) sm += __shfl_xor_sync(0xffffffffu, sm, off);
        float inv = 1.0f / sm;
        g_p[b * T_CAP + lane]      = x0 * inv;
        g_p[b * T_CAP + lane + 32] = x1 * inv;
    }
}

// ---------------- ctx[b,:] = sum_t p[b,t] * feats[b,t,:]  (BW streaming) ----------------
// one block per b; 256 threads; each thread owns 4 consecutive d (float4)
__global__ __launch_bounds__(256) void ctx_kernel(const float* __restrict__ dh)
{
    const int b = blockIdx.x, tid = threadIdx.x;
    __shared__ float p_s[T_CAP];
    if (tid < T_CAP) p_s[tid] = g_p[b * T_CAP + tid];
    __syncthreads();

    float4 acc = make_float4(0.f, 0.f, 0.f, 0.f);
    const int d = tid * 4;
#pragma unroll 8
    for (int t = 0; t < T_CAP; t++) {
        float p = p_s[t];
        float4 f = *(const float4*)&dh[(long)(t * BATCH + b) * DEC + d];
        acc.x += p * f.x; acc.y += p * f.y; acc.z += p * f.z; acc.w += p * f.w;
    }
    *(float4*)&g_ctx[b * DEC + d] = acc;
}

// ---------------- gates GEMM (tf32 mma) + fused LSTM pointwise ----------------
// gates = [ctx|h_prev](256x2048) @ [W_ih|W_hh]^T, gate-interleaved columns j=4*nl+gate.
// BM=128, BN(j)=64, grid (2, 64), 256 threads; warp tile 32x32 (warps 4m x 2n).
// 4-stage cp.async pipeline, BK=16, ONE __syncthreads per k-iter.
#define GK_A_FLOATS (4 * 128 * 20)
#define GK_B_FLOATS (4 * 64 * 20)
#define GK_SMEM_FLOATS (GK_A_FLOATS + GK_B_FLOATS)   // 15360 floats = 61440 B

__global__ __launch_bounds__(256) void gates_kernel(
    const float* __restrict__ W_ih, const float* __restrict__ W_hh,
    const float* __restrict__ b_ih, const float* __restrict__ b_hh,
    float* __restrict__ out, int step, int T_feat)
{
    extern __shared__ __align__(16) float smem[];
    __shared__ float bias_s[64];

    const int tid = threadIdx.x;
    const int m0 = blockIdx.x * 128;
    const int n0 = blockIdx.y * 16;
    const float* hprev = g_h[step & 1];
    float* hnext = g_h[(step + 1) & 1];

    if (tid < 64) {
        int row = (tid & 3) * 1024 + n0 + (tid >> 2);
        bias_s[tid] = b_ih[row] + b_hh[row];
    }

    const int am = tid >> 1;
    const int ak = (tid & 1) * 8;
    const int bj = tid >> 2;
    const int bk = (tid & 3) * 4;
    const long brow = (long)((bj & 3) * 1024 + n0 + (bj >> 2)) * 1024;
    const long arow = (long)(m0 + am) * 1024;

    const int warp = tid >> 5, lane = tid & 31;
    const int wm = (warp >> 1) * 32;     // 4 m-groups of 32
    const int wn = (warp & 1) * 32;      // 2 n-groups of 32
    const int lr = lane >> 2;
    const int lc = lane & 3;

    float* const Abase = smem;                 // [4][128][20]
    float* const Bbase = smem + GK_A_FLOATS;   // [4][64][20]

    float acc[2][4][4];
#pragma unroll
    for (int i = 0; i < 2; i++)
#pragma unroll
        for (int j = 0; j < 4; j++)
#pragma unroll
            for (int k = 0; k < 4; k++) acc[i][j][k] = 0.0f;

    const int NS = 2048 / 16;

    // prefetch stages 0,1 (both k<1024: A from ctx, B from W_ih)
#pragma unroll
    for (int s0 = 0; s0 < 2; s0++) {
        float* As = Abase + s0 * (128 * 20);
        float* Bs = Bbase + s0 * (64 * 20);
        int k0 = s0 * 16;
        cp16(As + am * 20 + ak,     g_ctx + arow + k0 + ak);
        cp16(As + am * 20 + ak + 4, g_ctx + arow + k0 + ak + 4);
        cp16(Bs + bj * 20 + bk,     W_ih + brow + k0 + bk);
        CP_COMMIT();
    }

    for (int s = 0; s < NS; s++) {
        if (s + 2 < NS) {
            int buf = (s + 2) & 3, k0 = (s + 2) * 16;
            const float* Asrc = (k0 < 1024) ? g_ctx : hprev;
            const float* Bsrc = (k0 < 1024) ? W_ih : W_hh;
            int kb = k0 & 1023;
            float* As = Abase + buf * (128 * 20);
            float* Bs = Bbase + buf * (64 * 20);
            cp16(As + am * 20 + ak,     Asrc + arow + kb + ak);
            cp16(As + am * 20 + ak + 4, Asrc + arow + kb + ak + 4);
            cp16(Bs + bj * 20 + bk,     Bsrc + brow + kb + bk);
            CP_COMMIT();
            CP_WAIT2();
        } else if (s + 1 < NS) {
            CP_WAIT1();
        } else {
            CP_WAIT0();
        }
        __syncthreads();

        const int buf = s & 3;
        const float* As = Abase + buf * (128 * 20);
        const float* Bs = Bbase + buf * (64 * 20);
#pragma unroll
        for (int kk = 0; kk < 16; kk += 8) {
            uint32_t af[2][4], bf[4][2];
#pragma unroll
            for (int fm = 0; fm < 2; fm++) {
                int rr = wm + fm * 16 + lr;
                af[fm][0] = f2tf(As[rr * 20 + kk + lc]);
                af[fm][1] = f2tf(As[(rr + 8) * 20 + kk + lc]);
                af[fm][2] = f2tf(As[rr * 20 + kk + lc + 4]);
                af[fm][3] = f2tf(As[(rr + 8) * 20 + kk + lc + 4]);
            }
#pragma unroll
            for (int fn = 0; fn < 4; fn++) {
                int jc = wn + fn * 8 + lr;
                bf[fn][0] = f2tf(Bs[jc * 20 + kk + lc]);
                bf[fn][1] = f2tf(Bs[jc * 20 + kk + lc + 4]);
            }
#pragma unroll
            for (int fm = 0; fm < 2; fm++)
#pragma unroll
                for (int fn = 0; fn < 4; fn++) mma8(acc[fm][fn], af[fm], bf[fn]);
        }
    }

    __syncthreads();  // all compute done before overlaying smem with gates tile

    // dump accumulators to smem gates tile [128][64] (stride 68)
    float (*gs)[68] = (float(*)[68])smem;
#pragma unroll
    for (int fm = 0; fm < 2; fm++) {
#pragma unroll
        for (int fn = 0; fn < 4; fn++) {
            int m = wm + fm * 16 + lr;
            int j = wn + fn * 8 + 2 * lc;
            *(float2*)&gs[m][j]     = make_float2(acc[fm][fn][0], acc[fm][fn][1]);
            *(float2*)&gs[m + 8][j] = make_float2(acc[fm][fn][2], acc[fm][fn][3]);
        }
    }
    __syncthreads();

    // fused LSTM pointwise: read (i,f,g,o) quadruple per (m, n)
    for (int q = tid; q < 128 * 16; q += 256) {
        int ml = q & 127, nl = q >> 7;
        float4 g4 = *(float4*)&gs[ml][nl * 4];
        float iv = g4.x + bias_s[nl * 4 + 0];
        float fv = g4.y + bias_s[nl * 4 + 1];
        float gv = g4.z + bias_s[nl * 4 + 2];
        float ov = g4.w + bias_s[nl * 4 + 3];
        int b = m0 + ml, n = n0 + nl;
        int idx = b * HID + n;
        float cold = g_c[idx];
        float cn = sigf(fv) * cold + sigf(iv) * tanhf(gv);
        float hn = sigf(ov) * tanhf(cn);
        g_c[idx] = cn;
        hnext[idx] = hn;
        out[(long)(b * T_feat + step) * HID + n] = hn;
    }
}

// ---------------- launcher ----------------
extern "C" void kernel_launch(void* const* d_in, const int* in_sizes, int n_in,
                              void* d_out, int out_size)
{
    int base = 2;
    if (n_in >= 11 && in_sizes[2] == 1) base = 3;

    const float* dh     = (const float*)d_in[0];
    const int*   caps   = (const int*)d_in[1];
    const float* W_attn = (const float*)d_in[base + 0];
    const float* U_attn = (const float*)d_in[base + 1];
    const float* b_attn = (const float*)d_in[base + 2];
    const float* w_attn = (const float*)d_in[base + 3];
    const float* W_ih   = (const float*)d_in[base + 4];
    const float* W_hh   = (const float*)d_in[base + 5];
    const float* b_ih   = (const float*)d_in[base + 6];
    const float* b_hh   = (const float*)d_in[base + 7];
    float* out = (float*)d_out;

    const int T_feat = out_size / (BATCH * HID);  // 28

    cudaFuncSetAttribute(gates_kernel, cudaFuncAttributeMaxDynamicSharedMemorySize,
                         GK_SMEM_FLOATS * sizeof(float));

    init_kernel<<<(BATCH * HID + 255) / 256, 256>>>();
    uv_kernel<<<dim3(128, 2), 256>>>(dh, U_attn, b_attn);

    for (int s = 0; s < T_feat; s++) {
        wh_kernel<<<dim3(8, 8), 256>>>(W_attn, s & 1);
        esoft_kernel<<<BATCH, 128>>>(caps, w_attn);
        ctx_kernel<<<BATCH, 256>>>(dh);
        gates_kernel<<<dim3(2, 64), 256, GK_SMEM_FLOATS * sizeof(float)>>>(
            W_ih, W_hh, b_ih, b_hh, out, s, T_feat);
    }
}

// round 3
// speedup vs baseline: 1.3268x; 1.3268x over previous
#include <cuda_runtime.h>
#include <cstdint>

#define T_CAP 64
#define BATCH 256
#define DEC   1024
#define HID   1024
#define ATTN  128
#define NBLK  128
#define NTHR  256

// ---------------- persistent scratch ----------------
__device__ float g_Uv[BATCH * T_CAP * ATTN];   // 8 MB, [b][t][a]
__device__ float g_h[2][BATCH * HID];          // double-buffered hidden
__device__ float g_c[BATCH * HID];             // cell state (block-private tiles)
__device__ float g_ctx[BATCH * DEC];           // per-step context
__device__ int   g_cnt;                        // barrier counter (returns to 0)
__device__ volatile int g_flag;                // barrier sense flag (returns to 0)

// ---------------- helpers ----------------
__device__ __forceinline__ uint32_t f2tf(float f) {
    uint32_t u;
    asm("cvt.rna.tf32.f32 %0, %1;" : "=r"(u) : "f"(f));
    return u;
}

__device__ __forceinline__ void mma8(float* c, const uint32_t* a, const uint32_t* b) {
    asm volatile(
        "mma.sync.aligned.m16n8k8.row.col.f32.tf32.tf32.f32 "
        "{%0,%1,%2,%3}, {%4,%5,%6,%7}, {%8,%9}, {%0,%1,%2,%3};\n"
        : "+f"(c[0]), "+f"(c[1]), "+f"(c[2]), "+f"(c[3])
        : "r"(a[0]), "r"(a[1]), "r"(a[2]), "r"(a[3]),
          "r"(b[0]), "r"(b[1]));
}

__device__ __forceinline__ void cp16(float* s, const float* g) {          // L1-cacheable (constants)
    uint32_t sa = (uint32_t)__cvta_generic_to_shared(s);
    asm volatile("cp.async.ca.shared.global [%0], [%1], 16;\n" :: "r"(sa), "l"(g));
}
__device__ __forceinline__ void cp16cg(float* s, const float* g) {        // L2-only (mutable data)
    uint32_t sa = (uint32_t)__cvta_generic_to_shared(s);
    asm volatile("cp.async.cg.shared.global [%0], [%1], 16;\n" :: "r"(sa), "l"(g));
}
#define CP_COMMIT() asm volatile("cp.async.commit_group;\n" ::)
#define CP_WAIT2()  asm volatile("cp.async.wait_group 2;\n" ::)
#define CP_WAIT1()  asm volatile("cp.async.wait_group 1;\n" ::)
#define CP_WAIT0()  asm volatile("cp.async.wait_group 0;\n" ::)

__device__ __forceinline__ float sigf(float x) { return 1.0f / (1.0f + __expf(-x)); }
__device__ __forceinline__ float tanh_fast(float x) {
    return __fdividef(2.0f, 1.0f + __expf(-2.0f * x)) - 1.0f;
}

// sense-reversing grid barrier (all NBLK blocks are co-resident by construction)
__device__ __forceinline__ void gsync(int* sense) {
    __syncthreads();
    int s = *sense ^ 1;
    *sense = s;
    if (threadIdx.x == 0) {
        __threadfence();
        if (atomicAdd(&g_cnt, 1) == NBLK - 1) {
            g_cnt = 0;
            __threadfence();
            g_flag = s;
        } else {
            while (g_flag != s) __nanosleep(32);
        }
        __threadfence();
    }
    __syncthreads();
}

// ---------------- Uv tile: 128(m) x 64(n) x 1024(k) tf32 mma ----------------
__device__ __forceinline__ void uv_tile(
    float* smem, const float* __restrict__ dh, const float* __restrict__ U_attn,
    const float* __restrict__ b_attn, int m0, int n0)
{
    float (*As)[128][20] = (float(*)[128][20])smem;           // 2*128*20
    float (*Bs)[64][20]  = (float(*)[64][20])(smem + 5120);   // 2*64*20

    const int tid = threadIdx.x;
    const int am = tid >> 1;
    const int ak = (tid & 1) * 8;
    const int bj = tid >> 2;
    const int bk = (tid & 3) * 4;

    const int r = m0 + am;                                     // Uv row = b*64 + t
    const long abase = ((long)((r & 63) * 256 + (r >> 6))) * 1024;
    const long bbase = (long)(n0 + bj) * 1024;

    const int warp = tid >> 5, lane = tid & 31;
    const int wm = (warp >> 2) * 64;
    const int wn = (warp & 3) * 16;
    const int lr = lane >> 2;
    const int lc = lane & 3;

    float acc[4][2][4];
#pragma unroll
    for (int i = 0; i < 4; i++)
#pragma unroll
        for (int j = 0; j < 2; j++)
#pragma unroll
            for (int k = 0; k < 4; k++) acc[i][j][k] = 0.0f;

    const int NS = 1024 / 16;
    cp16(&As[0][am][ak],     dh + abase + ak);
    cp16(&As[0][am][ak + 4], dh + abase + ak + 4);
    cp16(&Bs[0][bj][bk],     U_attn + bbase + bk);
    CP_COMMIT();

    for (int s = 0; s < NS; s++) {
        if (s + 1 < NS) {
            int buf = (s + 1) & 1, k0 = (s + 1) * 16;
            cp16(&As[buf][am][ak],     dh + abase + k0 + ak);
            cp16(&As[buf][am][ak + 4], dh + abase + k0 + ak + 4);
            cp16(&Bs[buf][bj][bk],     U_attn + bbase + k0 + bk);
            CP_COMMIT();
            CP_WAIT1();
        } else {
            CP_WAIT0();
        }
        __syncthreads();
        const int buf = s & 1;
#pragma unroll
        for (int kk = 0; kk < 16; kk += 8) {
            uint32_t af[4][4], bf[2][2];
#pragma unroll
            for (int fm = 0; fm < 4; fm++) {
                int rr = wm + fm * 16 + lr;
                af[fm][0] = f2tf(As[buf][rr][kk + lc]);
                af[fm][1] = f2tf(As[buf][rr + 8][kk + lc]);
                af[fm][2] = f2tf(As[buf][rr][kk + lc + 4]);
                af[fm][3] = f2tf(As[buf][rr + 8][kk + lc + 4]);
            }
#pragma unroll
            for (int fn = 0; fn < 2; fn++) {
                int jc = wn + fn * 8 + lr;
                bf[fn][0] = f2tf(Bs[buf][jc][kk + lc]);
                bf[fn][1] = f2tf(Bs[buf][jc][kk + lc + 4]);
            }
#pragma unroll
            for (int fm = 0; fm < 4; fm++)
#pragma unroll
                for (int fn = 0; fn < 2; fn++) mma8(acc[fm][fn], af[fm], bf[fn]);
        }
        __syncthreads();
    }

#pragma unroll
    for (int fm = 0; fm < 4; fm++) {
#pragma unroll
        for (int fn = 0; fn < 2; fn++) {
            int rr = m0 + wm + fm * 16 + lr;
            int a  = n0 + wn + fn * 8 + 2 * lc;
            float ba0 = b_attn[a], ba1 = b_attn[a + 1];
            float2 v0 = make_float2(acc[fm][fn][0] + ba0, acc[fm][fn][1] + ba1);
            float2 v1 = make_float2(acc[fm][fn][2] + ba0, acc[fm][fn][3] + ba1);
            *(float2*)&g_Uv[rr * ATTN + a]       = v0;
            *(float2*)&g_Uv[(rr + 8) * ATTN + a] = v1;
        }
    }
}

// ---------------- the persistent kernel ----------------
#define GK_SMEM_FLOATS (4 * 128 * 20 + 4 * 64 * 20)   // 15360 floats = 61440 B

__global__ __launch_bounds__(NTHR, 1) void recon_kernel(
    const float* __restrict__ dh, const int* __restrict__ caps,
    const float* __restrict__ W_attn, const float* __restrict__ U_attn,
    const float* __restrict__ b_attn, const float* __restrict__ w_attn,
    const float* __restrict__ W_ih, const float* __restrict__ W_hh,
    const float* __restrict__ b_ih, const float* __restrict__ b_hh,
    float* __restrict__ out, int T_feat)
{
    extern __shared__ __align__(16) float smem[];
    __shared__ float bias_s[64];

    const int tid = threadIdx.x, blk = blockIdx.x;
    const int warp = tid >> 5, lane = tid & 31;
    int sense = 0;

    // gates tile owned by this block (fixed across steps -> g_c block-private)
    const int gm0 = (blk & 1) * 128;
    const int gn0 = (blk >> 1) * 16;

    if (tid < 64) {
        int row = (tid & 3) * 1024 + gn0 + (tid >> 2);
        bias_s[tid] = b_ih[row] + b_hh[row];
    }

    // ---- phase 0: zero h0/c, compute Uv (2 tiles per block) ----
    for (int i = blk * NTHR + tid; i < BATCH * HID; i += NBLK * NTHR) {
        g_h[0][i] = 0.0f;
        g_c[i]    = 0.0f;
    }
    for (int tix = blk; tix < 256; tix += NBLK)
        uv_tile(smem, dh, U_attn, b_attn, (tix & 127) * 128, (tix >> 7) * 64);
    gsync(&sense);

    for (int s = 0; s < T_feat; s++) {
        const float* hprev = g_h[s & 1];
        float* hnext = g_h[(s + 1) & 1];

        // ================= attention phase: 2 batch rows per block =================
        {
            const int b0 = blk * 2;
            float* hs  = smem;           // [2][1024]
            float* whs = smem + 2048;    // [2][128]
            float* wa  = smem + 2304;    // [128]
            float* es  = smem + 2432;    // [2][64]
            float* ps  = smem + 2560;    // [2][64]

            for (int i = tid; i < 2 * HID; i += NTHR)
                hs[i] = __ldcg(&hprev[b0 * HID + i]);
            if (tid < ATTN) wa[tid] = w_attn[tid];
            __syncthreads();

            // Wh[bi][a] = h[bi] . W_attn[a]  — warp w owns a in [16w, 16w+16)
            const float4* h0v = (const float4*)hs;
            const float4* h1v = (const float4*)(hs + 1024);
            for (int rr = 0; rr < 16; rr++) {
                int a = warp * 16 + rr;
                const float4* wrow = (const float4*)(W_attn + a * 1024);
                float d0 = 0.f, d1 = 0.f;
#pragma unroll
                for (int j = 0; j < 8; j++) {
                    float4 w4 = wrow[lane + 32 * j];
                    float4 x4 = h0v[lane + 32 * j];
                    float4 y4 = h1v[lane + 32 * j];
                    d0 += w4.x * x4.x + w4.y * x4.y + w4.z * x4.z + w4.w * x4.w;
                    d1 += w4.x * y4.x + w4.y * y4.y + w4.z * y4.z + w4.w * y4.w;
                }
#pragma unroll
                for (int off = 16; off; off >>= 1) {
                    d0 += __shfl_xor_sync(0xffffffffu, d0, off);
                    d1 += __shfl_xor_sync(0xffffffffu, d1, off);
                }
                if (lane == 0) { whs[a] = d0; whs[128 + a] = d1; }
            }
            __syncthreads();

            // energies
            for (int t = warp; t < T_CAP; t += 8) {
#pragma unroll
                for (int bi = 0; bi < 2; bi++) {
                    const float* uv = g_Uv + ((long)(b0 + bi) * T_CAP + t) * ATTN;
                    float sE = 0.f;
#pragma unroll
                    for (int q = 0; q < 4; q++) {
                        int a = lane + q * 32;
                        sE += wa[a] * tanh_fast(whs[bi * 128 + a] + uv[a]);
                    }
#pragma unroll
                    for (int off = 16; off; off >>= 1)
                        sE += __shfl_xor_sync(0xffffffffu, sE, off);
                    if (lane == 0) {
                        int cp = caps[t * BATCH + b0 + bi];
                        es[bi * 64 + t] = (cp != 0 && cp != 2) ? sE : -1e30f;
                    }
                }
            }
            __syncthreads();

            // masked softmax (warp 0 -> bi 0, warp 1 -> bi 1)
            if (warp < 2) {
                int bi = warp;
                float e0 = es[bi * 64 + lane], e1 = es[bi * 64 + lane + 32];
                float mx = fmaxf(e0, e1);
#pragma unroll
                for (int off = 16; off; off >>= 1)
                    mx = fmaxf(mx, __shfl_xor_sync(0xffffffffu, mx, off));
                float x0 = __expf(e0 - mx), x1 = __expf(e1 - mx);
                float sm = x0 + x1;
#pragma unroll
                for (int off = 16; off; off >>= 1)
                    sm += __shfl_xor_sync(0xffffffffu, sm, off);
                float inv = 1.0f / sm;
                ps[bi * 64 + lane]      = x0 * inv;
                ps[bi * 64 + lane + 32] = x1 * inv;
            }
            __syncthreads();

            // ctx: thread owns 4 consecutive d
            {
                float4 a0 = make_float4(0.f, 0.f, 0.f, 0.f);
                float4 a1 = a0;
#pragma unroll 4
                for (int t = 0; t < T_CAP; t++) {
                    float p0 = ps[t], p1 = ps[64 + t];
                    float4 x = ((const float4*)(dh + (long)(t * BATCH + b0) * DEC))[tid];
                    float4 y = ((const float4*)(dh + (long)(t * BATCH + b0 + 1) * DEC))[tid];
                    a0.x += p0 * x.x; a0.y += p0 * x.y; a0.z += p0 * x.z; a0.w += p0 * x.w;
                    a1.x += p1 * y.x; a1.y += p1 * y.y; a1.z += p1 * y.z; a1.w += p1 * y.w;
                }
                ((float4*)&g_ctx[(long)b0 * DEC])[tid]       = a0;
                ((float4*)&g_ctx[(long)(b0 + 1) * DEC])[tid] = a1;
            }
        }
        gsync(&sense);

        // ================= gates phase: 128x16(x4 gates) tile, tf32 mma =================
        {
            const int am = tid >> 1;
            const int ak = (tid & 1) * 8;
            const int bj = tid >> 2;
            const int bk = (tid & 3) * 4;
            const long brow = (long)((bj & 3) * 1024 + gn0 + (bj >> 2)) * 1024;
            const long arow = (long)(gm0 + am) * 1024;

            const int wm = (warp >> 1) * 32;
            const int wn = (warp & 1) * 32;
            const int lr = lane >> 2;
            const int lc = lane & 3;

            float* const Abase = smem;                     // [4][128][20]
            float* const Bbase = smem + 4 * 128 * 20;      // [4][64][20]

            float acc[2][4][4];
#pragma unroll
            for (int i = 0; i < 2; i++)
#pragma unroll
                for (int j = 0; j < 4; j++)
#pragma unroll
                    for (int k = 0; k < 4; k++) acc[i][j][k] = 0.0f;

            const int NS = 2048 / 16;
#pragma unroll
            for (int s0 = 0; s0 < 2; s0++) {
                float* As = Abase + s0 * (128 * 20);
                float* Bs = Bbase + s0 * (64 * 20);
                int k0 = s0 * 16;
                cp16cg(As + am * 20 + ak,     g_ctx + arow + k0 + ak);
                cp16cg(As + am * 20 + ak + 4, g_ctx + arow + k0 + ak + 4);
                cp16(Bs + bj * 20 + bk,       W_ih + brow + k0 + bk);
                CP_COMMIT();
            }

            for (int ks = 0; ks < NS; ks++) {
                if (ks + 2 < NS) {
                    int buf = (ks + 2) & 3, k0 = (ks + 2) * 16;
                    const float* Asrc = (k0 < 1024) ? g_ctx : hprev;
                    const float* Bsrc = (k0 < 1024) ? W_ih : W_hh;
                    int kb = k0 & 1023;
                    float* As = Abase + buf * (128 * 20);
                    float* Bs = Bbase + buf * (64 * 20);
                    cp16cg(As + am * 20 + ak,     Asrc + arow + kb + ak);
                    cp16cg(As + am * 20 + ak + 4, Asrc + arow + kb + ak + 4);
                    cp16(Bs + bj * 20 + bk,       Bsrc + brow + kb + bk);
                    CP_COMMIT();
                    CP_WAIT2();
                } else if (ks + 1 < NS) {
                    CP_WAIT1();
                } else {
                    CP_WAIT0();
                }
                __syncthreads();

                const int buf = ks & 3;
                const float* As = Abase + buf * (128 * 20);
                const float* Bs = Bbase + buf * (64 * 20);
#pragma unroll
                for (int kk = 0; kk < 16; kk += 8) {
                    uint32_t af[2][4], bf[4][2];
#pragma unroll
                    for (int fm = 0; fm < 2; fm++) {
                        int rr = wm + fm * 16 + lr;
                        af[fm][0] = f2tf(As[rr * 20 + kk + lc]);
                        af[fm][1] = f2tf(As[(rr + 8) * 20 + kk + lc]);
                        af[fm][2] = f2tf(As[rr * 20 + kk + lc + 4]);
                        af[fm][3] = f2tf(As[(rr + 8) * 20 + kk + lc + 4]);
                    }
#pragma unroll
                    for (int fn = 0; fn < 4; fn++) {
                        int jc = wn + fn * 8 + lr;
                        bf[fn][0] = f2tf(Bs[jc * 20 + kk + lc]);
                        bf[fn][1] = f2tf(Bs[jc * 20 + kk + lc + 4]);
                    }
#pragma unroll
                    for (int fm = 0; fm < 2; fm++)
#pragma unroll
                        for (int fn = 0; fn < 4; fn++) mma8(acc[fm][fn], af[fm], bf[fn]);
                }
            }

            __syncthreads();

            float (*gs)[68] = (float(*)[68])smem;
#pragma unroll
            for (int fm = 0; fm < 2; fm++) {
#pragma unroll
                for (int fn = 0; fn < 4; fn++) {
                    int m = wm + fm * 16 + lr;
                    int j = wn + fn * 8 + 2 * lc;
                    *(float2*)&gs[m][j]     = make_float2(acc[fm][fn][0], acc[fm][fn][1]);
                    *(float2*)&gs[m + 8][j] = make_float2(acc[fm][fn][2], acc[fm][fn][3]);
                }
            }
            __syncthreads();

            for (int q = tid; q < 128 * 16; q += NTHR) {
                int ml = q & 127, nl = q >> 7;
                float4 g4 = *(float4*)&gs[ml][nl * 4];
                float iv = g4.x + bias_s[nl * 4 + 0];
                float fv = g4.y + bias_s[nl * 4 + 1];
                float gv = g4.z + bias_s[nl * 4 + 2];
                float ov = g4.w + bias_s[nl * 4 + 3];
                int b = gm0 + ml, n = gn0 + nl;
                int idx = b * HID + n;
                float cold = g_c[idx];
                float cn = sigf(fv) * cold + sigf(iv) * tanhf(gv);
                float hn = sigf(ov) * tanhf(cn);
                g_c[idx] = cn;
                hnext[idx] = hn;
                out[(long)(b * T_feat + s) * HID + n] = hn;
            }
        }
        gsync(&sense);
    }

    gsync(&sense);  // parity: total barrier count even -> g_flag restored to 0
}

// ---------------- launcher ----------------
extern "C" void kernel_launch(void* const* d_in, const int* in_sizes, int n_in,
                              void* d_out, int out_size)
{
    int base = 2;
    if (n_in >= 11 && in_sizes[2] == 1) base = 3;

    const float* dh     = (const float*)d_in[0];
    const int*   caps   = (const int*)d_in[1];
    const float* W_attn = (const float*)d_in[base + 0];
    const float* U_attn = (const float*)d_in[base + 1];
    const float* b_attn = (const float*)d_in[base + 2];
    const float* w_attn = (const float*)d_in[base + 3];
    const float* W_ih   = (const float*)d_in[base + 4];
    const float* W_hh   = (const float*)d_in[base + 5];
    const float* b_ih   = (const float*)d_in[base + 6];
    const float* b_hh   = (const float*)d_in[base + 7];
    float* out = (float*)d_out;

    const int T_feat = out_size / (BATCH * HID);  // 28

    static int configured = 0;
    if (!configured) {
        cudaFuncSetAttribute(recon_kernel, cudaFuncAttributeMaxDynamicSharedMemorySize,
                             GK_SMEM_FLOATS * sizeof(float));
        configured = 1;
    }

    recon_kernel<<<NBLK, NTHR, GK_SMEM_FLOATS * sizeof(float)>>>(
        dh, caps, W_attn, U_attn, b_attn, w_attn,
        W_ih, W_hh, b_ih, b_hh, out, T_feat);
}

// round 5
// speedup vs baseline: 1.5569x; 1.1734x over previous
#include <cuda_runtime.h>
#include <cstdint>

#define T_CAP 64
#define BATCH 256
#define DEC   1024
#define HID   1024
#define ATTN  128
#define NBLK  128
#define NTHR  256

// ---------------- persistent scratch ----------------
__device__ float g_Uv[BATCH * T_CAP * ATTN];   // 8 MB, [b][t][a]
__device__ float g_h[2][BATCH * HID];          // double-buffered hidden (tf32-rounded)
__device__ float g_c[BATCH * HID];             // cell state (block-private tiles)
__device__ float g_ctx[BATCH * DEC];           // per-step context (tf32-rounded)
__device__ float g_Wih_r[4 * HID * DEC];       // tf32-rounded W_ih, gate rows as-is
__device__ float g_Whh_r[4 * HID * HID];       // tf32-rounded W_hh
__device__ int   g_cnt;
__device__ volatile int g_flag;

// ---------------- helpers ----------------
__device__ __forceinline__ uint32_t f2tf(float f) {
    uint32_t u;
    asm("cvt.rna.tf32.f32 %0, %1;" : "=r"(u) : "f"(f));
    return u;
}
__device__ __forceinline__ float round_tf32(float f) { return __uint_as_float(f2tf(f)); }

__device__ __forceinline__ void mma8(float* c, const uint32_t* a, const uint32_t* b) {
    asm volatile(
        "mma.sync.aligned.m16n8k8.row.col.f32.tf32.tf32.f32 "
        "{%0,%1,%2,%3}, {%4,%5,%6,%7}, {%8,%9}, {%0,%1,%2,%3};\n"
        : "+f"(c[0]), "+f"(c[1]), "+f"(c[2]), "+f"(c[3])
        : "r"(a[0]), "r"(a[1]), "r"(a[2]), "r"(a[3]),
          "r"(b[0]), "r"(b[1]));
}

__device__ __forceinline__ void ldsm4(uint32_t* r, uint32_t addr) {
    asm volatile("ldmatrix.sync.aligned.m8n8.x4.shared.b16 {%0,%1,%2,%3}, [%4];"
                 : "=r"(r[0]), "=r"(r[1]), "=r"(r[2]), "=r"(r[3]) : "r"(addr));
}

__device__ __forceinline__ uint32_t smem_u32(const void* p) {
    return (uint32_t)__cvta_generic_to_shared(p);
}
__device__ __forceinline__ void cp16(void* s, const float* g) {
    asm volatile("cp.async.ca.shared.global [%0], [%1], 16;\n" :: "r"(smem_u32(s)), "l"(g));
}
__device__ __forceinline__ void cp16cg(void* s, const float* g) {
    asm volatile("cp.async.cg.shared.global [%0], [%1], 16;\n" :: "r"(smem_u32(s)), "l"(g));
}
#define CP_COMMIT() asm volatile("cp.async.commit_group;\n" ::)
#define CP_WAIT2()  asm volatile("cp.async.wait_group 2;\n" ::)
#define CP_WAIT1()  asm volatile("cp.async.wait_group 1;\n" ::)
#define CP_WAIT0()  asm volatile("cp.async.wait_group 0;\n" ::)

__device__ __forceinline__ float sigf(float x) { return 1.0f / (1.0f + __expf(-x)); }
__device__ __forceinline__ float tanh_fast(float x) {
    return __fdividef(2.0f, 1.0f + __expf(-2.0f * x)) - 1.0f;
}

#define SWZ(x) ((x) ^ (((x) >> 3) & 0x70))

// grid barrier (all NBLK blocks co-resident)
__device__ __forceinline__ void gsync(int* sense) {
    __syncthreads();
    int s = *sense ^ 1;
    *sense = s;
    if (threadIdx.x == 0) {
        __threadfence();
        if (atomicAdd(&g_cnt, 1) == NBLK - 1) {
            g_cnt = 0;
            __threadfence();
            g_flag = s;
        } else {
            while (g_flag != s) __nanosleep(32);
        }
        __threadfence();
    }
    __syncthreads();
}

// ---------------- Uv tile: 128(m) x 64(n) x 1024(k) tf32 mma.sync (one-time) ----------------
__device__ __forceinline__ void uv_tile(
    float* smem, const float* __restrict__ dh, const float* __restrict__ U_attn,
    const float* __restrict__ b_attn, int m0, int n0)
{
    float (*As)[128][20] = (float(*)[128][20])smem;
    float (*Bs)[64][20]  = (float(*)[64][20])(smem + 5120);

    const int tid = threadIdx.x;
    const int am = tid >> 1, ak = (tid & 1) * 8;
    const int bj = tid >> 2, bk = (tid & 3) * 4;
    const int r = m0 + am;
    const long abase = ((long)((r & 63) * 256 + (r >> 6))) * 1024;
    const long bbase = (long)(n0 + bj) * 1024;

    const int warp = tid >> 5, lane = tid & 31;
    const int wm = (warp >> 2) * 64, wn = (warp & 3) * 16;
    const int lr = lane >> 2, lc = lane & 3;

    float acc[4][2][4];
#pragma unroll
    for (int i = 0; i < 4; i++)
#pragma unroll
        for (int j = 0; j < 2; j++)
#pragma unroll
            for (int k = 0; k < 4; k++) acc[i][j][k] = 0.0f;

    const int NS = 64;
    cp16(&As[0][am][ak],     dh + abase + ak);
    cp16(&As[0][am][ak + 4], dh + abase + ak + 4);
    cp16(&Bs[0][bj][bk],     U_attn + bbase + bk);
    CP_COMMIT();

    for (int s = 0; s < NS; s++) {
        if (s + 1 < NS) {
            int buf = (s + 1) & 1, k0 = (s + 1) * 16;
            cp16(&As[buf][am][ak],     dh + abase + k0 + ak);
            cp16(&As[buf][am][ak + 4], dh + abase + k0 + ak + 4);
            cp16(&Bs[buf][bj][bk],     U_attn + bbase + k0 + bk);
            CP_COMMIT();
            CP_WAIT1();
        } else {
            CP_WAIT0();
        }
        __syncthreads();
        const int buf = s & 1;
#pragma unroll
        for (int kk = 0; kk < 16; kk += 8) {
            uint32_t af[4][4], bf[2][2];
#pragma unroll
            for (int fm = 0; fm < 4; fm++) {
                int rr = wm + fm * 16 + lr;
                af[fm][0] = f2tf(As[buf][rr][kk + lc]);
                af[fm][1] = f2tf(As[buf][rr + 8][kk + lc]);
                af[fm][2] = f2tf(As[buf][rr][kk + lc + 4]);
                af[fm][3] = f2tf(As[buf][rr + 8][kk + lc + 4]);
            }
#pragma unroll
            for (int fn = 0; fn < 2; fn++) {
                int jc = wn + fn * 8 + lr;
                bf[fn][0] = f2tf(Bs[buf][jc][kk + lc]);
                bf[fn][1] = f2tf(Bs[buf][jc][kk + lc + 4]);
            }
#pragma unroll
            for (int fm = 0; fm < 4; fm++)
#pragma unroll
                for (int fn = 0; fn < 2; fn++) mma8(acc[fm][fn], af[fm], bf[fn]);
        }
        __syncthreads();
    }

#pragma unroll
    for (int fm = 0; fm < 4; fm++) {
#pragma unroll
        for (int fn = 0; fn < 2; fn++) {
            int rr = m0 + wm + fm * 16 + lr;
            int a  = n0 + wn + fn * 8 + 2 * lc;
            float ba0 = b_attn[a], ba1 = b_attn[a + 1];
            float2 v0 = make_float2(acc[fm][fn][0] + ba0, acc[fm][fn][1] + ba1);
            float2 v1 = make_float2(acc[fm][fn][2] + ba0, acc[fm][fn][3] + ba1);
            *(float2*)&g_Uv[rr * ATTN + a]       = v0;
            *(float2*)&g_Uv[(rr + 8) * ATTN + a] = v1;
        }
    }
}

// smem (dynamic, bytes): A stages [0,65536) 4x16KB ; B stages [65536,98304) 4x8KB
#define SM_A(sl)  ((sl) * 16384)
#define SM_B(sl)  (65536 + (sl) * 8192)
#define GK_SMEM_BYTES 98304

// ---------------- the persistent kernel ----------------
__global__ __launch_bounds__(NTHR, 1) void recon_kernel(
    const float* __restrict__ dh, const int* __restrict__ caps,
    const float* __restrict__ W_attn, const float* __restrict__ U_attn,
    const float* __restrict__ b_attn, const float* __restrict__ w_attn,
    const float* __restrict__ W_ih, const float* __restrict__ W_hh,
    const float* __restrict__ b_ih, const float* __restrict__ b_hh,
    float* __restrict__ out, int T_feat)
{
    extern __shared__ __align__(1024) float smem[];
    __shared__ float bias_s[64];

    const int tid = threadIdx.x, blk = blockIdx.x;
    const int warp = tid >> 5, lane = tid & 31;
    int sense = 0;

    const int gm0 = (blk & 1) * 128;
    const int gn0 = (blk >> 1) * 16;

    char* smem_c = (char*)smem;
    const uint32_t smem_base = smem_u32(smem);

    if (tid < 64) {
        int row = (tid & 3) * 1024 + gn0 + (tid >> 2);
        bias_s[tid] = b_ih[row] + b_hh[row];
    }

    // ---- phase 0: zero h/c, round weights to tf32, compute Uv ----
    for (int i = blk * NTHR + tid; i < BATCH * HID; i += NBLK * NTHR) {
        g_h[0][i] = 0.0f;
        g_c[i]    = 0.0f;
    }
    for (int i = blk * NTHR + tid; i < 4 * HID * DEC; i += NBLK * NTHR)
        g_Wih_r[i] = round_tf32(W_ih[i]);
    for (int i = blk * NTHR + tid; i < 4 * HID * HID; i += NBLK * NTHR)
        g_Whh_r[i] = round_tf32(W_hh[i]);
    for (int tix = blk; tix < 256; tix += NBLK)
        uv_tile(smem, dh, U_attn, b_attn, (tix & 127) * 128, (tix >> 7) * 64);
    gsync(&sense);

    // ---- gates loader indices (cp.async) ----
    const int a_row = tid >> 1, a_kf = (tid & 1) * 16;
    const int b_row = tid >> 2, b_kf = (tid & 3) * 8;
    const long a_goff = (long)(gm0 + a_row) * 1024 + a_kf;
    const long b_goff = (long)((b_row & 3) * 1024 + gn0 + (b_row >> 2)) * 1024 + b_kf;
    const int a_so = a_row * 128 + a_kf * 4;   // byte offset in A stage tile
    const int b_so = b_row * 128 + b_kf * 4;

    // ---- ldmatrix lane mapping: quad q = lane>>3 selects (row+8?, col+16B?) ----
    const int wm = (warp >> 1) * 32;   // 4 m-groups of 32
    const int wn = (warp & 1) * 32;    // 2 j-groups of 32
    {
    }
    const int ls_row = ((lane >> 3) & 1) * 8 + (lane & 7);
    const int ls_colb = (lane >> 4) * 16;              // 0 or 16 bytes
    const uint32_t a_swz = SWZ((uint32_t)((wm + ls_row) * 128 + ls_colb));
    const uint32_t b_swz = SWZ((uint32_t)((wn + ls_row) * 128 + ls_colb));

    const int lr = lane >> 2, lc = lane & 3;

    for (int s = 0; s < T_feat; s++) {
        const float* hprev = g_h[s & 1];
        float* hnext = g_h[(s + 1) & 1];

        // ================= attention: 2 batch rows per block =================
        {
            const int b0 = blk * 2;
            float* hs  = smem;           // [2][1024]
            float* whs = smem + 2048;    // [2][128]
            float* wa  = smem + 2304;    // [128]
            float* es  = smem + 2432;    // [2][64]
            float* ps  = smem + 2560;    // [2][64]

            for (int i = tid; i < 2 * HID; i += NTHR)
                hs[i] = __ldcg(&hprev[b0 * HID + i]);
            if (tid < ATTN) wa[tid] = w_attn[tid];
            __syncthreads();

            const float4* h0v = (const float4*)hs;
            const float4* h1v = (const float4*)(hs + 1024);
            for (int rr = 0; rr < 16; rr++) {
                int a = warp * 16 + rr;
                const float4* wrow = (const float4*)(W_attn + a * 1024);
                float d0 = 0.f, d1 = 0.f;
#pragma unroll
                for (int j = 0; j < 8; j++) {
                    float4 w4 = wrow[lane + 32 * j];
                    float4 x4 = h0v[lane + 32 * j];
                    float4 y4 = h1v[lane + 32 * j];
                    d0 += w4.x * x4.x + w4.y * x4.y + w4.z * x4.z + w4.w * x4.w;
                    d1 += w4.x * y4.x + w4.y * y4.y + w4.z * y4.z + w4.w * y4.w;
                }
#pragma unroll
                for (int off = 16; off; off >>= 1) {
                    d0 += __shfl_xor_sync(0xffffffffu, d0, off);
                    d1 += __shfl_xor_sync(0xffffffffu, d1, off);
                }
                if (lane == 0) { whs[a] = d0; whs[128 + a] = d1; }
            }
            __syncthreads();

            for (int t = warp; t < T_CAP; t += 8) {
#pragma unroll
                for (int bi = 0; bi < 2; bi++) {
                    const float* uv = g_Uv + ((long)(b0 + bi) * T_CAP + t) * ATTN;
                    float sE = 0.f;
#pragma unroll
                    for (int q = 0; q < 4; q++) {
                        int a = lane + q * 32;
                        sE += wa[a] * tanh_fast(whs[bi * 128 + a] + uv[a]);
                    }
#pragma unroll
                    for (int off = 16; off; off >>= 1)
                        sE += __shfl_xor_sync(0xffffffffu, sE, off);
                    if (lane == 0) {
                        int cp = caps[t * BATCH + b0 + bi];
                        es[bi * 64 + t] = (cp != 0 && cp != 2) ? sE : -1e30f;
                    }
                }
            }
            __syncthreads();

            if (warp < 2) {
                int bi = warp;
                float e0 = es[bi * 64 + lane], e1 = es[bi * 64 + lane + 32];
                float mx = fmaxf(e0, e1);
#pragma unroll
                for (int off = 16; off; off >>= 1)
                    mx = fmaxf(mx, __shfl_xor_sync(0xffffffffu, mx, off));
                float x0 = __expf(e0 - mx), x1 = __expf(e1 - mx);
                float sm = x0 + x1;
#pragma unroll
                for (int off = 16; off; off >>= 1)
                    sm += __shfl_xor_sync(0xffffffffu, sm, off);
                float inv = 1.0f / sm;
                ps[bi * 64 + lane]      = x0 * inv;
                ps[bi * 64 + lane + 32] = x1 * inv;
            }
            __syncthreads();

            {
                float4 a0 = make_float4(0.f, 0.f, 0.f, 0.f);
                float4 a1 = a0;
#pragma unroll 4
                for (int t = 0; t < T_CAP; t++) {
                    float p0 = ps[t], p1 = ps[64 + t];
                    float4 x = ((const float4*)(dh + (long)(t * BATCH + b0) * DEC))[tid];
                    float4 y = ((const float4*)(dh + (long)(t * BATCH + b0 + 1) * DEC))[tid];
                    a0.x += p0 * x.x; a0.y += p0 * x.y; a0.z += p0 * x.z; a0.w += p0 * x.w;
                    a1.x += p1 * y.x; a1.y += p1 * y.y; a1.z += p1 * y.z; a1.w += p1 * y.w;
                }
                a0.x = round_tf32(a0.x); a0.y = round_tf32(a0.y);
                a0.z = round_tf32(a0.z); a0.w = round_tf32(a0.w);
                a1.x = round_tf32(a1.x); a1.y = round_tf32(a1.y);
                a1.z = round_tf32(a1.z); a1.w = round_tf32(a1.w);
                ((float4*)&g_ctx[(long)b0 * DEC])[tid]       = a0;
                ((float4*)&g_ctx[(long)(b0 + 1) * DEC])[tid] = a1;
            }
        }
        gsync(&sense);

        // ===== gates: 128(m) x 64(j) x 2048(k), mma.sync tf32 + LDSM fragments =====
        {
            const int NS = 64;  // BK=32

            auto load_stage = [&](int ks) {
                int sl = ks & 3;
                int k0 = ks * 32;
                int kb = k0 & 1023;
                const float* Asrc = ((k0 < 1024) ? g_ctx : hprev) + a_goff + kb;
                const float* Bsrc = ((k0 < 1024) ? g_Wih_r : g_Whh_r) + b_goff + kb;
                char* Ab = smem_c + SM_A(sl);
                char* Bb = smem_c + SM_B(sl);
#pragma unroll
                for (int j = 0; j < 4; j++)
                    cp16cg(Ab + SWZ(a_so + j * 16), Asrc + j * 4);
#pragma unroll
                for (int j = 0; j < 2; j++)
                    cp16(Bb + SWZ(b_so + j * 16), Bsrc + j * 4);
                CP_COMMIT();
            };

            float acc[2][4][4];
#pragma unroll
            for (int i = 0; i < 2; i++)
#pragma unroll
                for (int j = 0; j < 4; j++)
#pragma unroll
                    for (int k = 0; k < 4; k++) acc[i][j][k] = 0.0f;

            load_stage(0);
            load_stage(1);

            for (int ks = 0; ks < NS; ks++) {
                if (ks + 2 < NS) {
                    load_stage(ks + 2);
                    CP_WAIT2();
                } else if (ks + 1 < NS) {
                    CP_WAIT1();
                } else {
                    CP_WAIT0();
                }
                __syncthreads();

                const int sl = ks & 3;
                const uint32_t Ab = smem_base + SM_A(sl);
                const uint32_t Bb = smem_base + SM_B(sl);
#pragma unroll
                for (int kk = 0; kk < 4; kk++) {
                    const uint32_t kofs = (uint32_t)(kk * 32);
                    uint32_t af[2][4], bfa[4], bfb[4];
                    ldsm4(af[0], Ab + (a_swz ^ kofs));
                    ldsm4(af[1], Ab + 2048 + (a_swz ^ kofs));
                    ldsm4(bfa,   Bb + (b_swz ^ kofs));
                    ldsm4(bfb,   Bb + 2048 + (b_swz ^ kofs));
                    uint32_t b0[2] = {bfa[0], bfa[2]};
                    uint32_t b1[2] = {bfa[1], bfa[3]};
                    uint32_t b2[2] = {bfb[0], bfb[2]};
                    uint32_t b3[2] = {bfb[1], bfb[3]};
#pragma unroll
                    for (int fm = 0; fm < 2; fm++) {
                        mma8(acc[fm][0], af[fm], b0);
                        mma8(acc[fm][1], af[fm], b1);
                        mma8(acc[fm][2], af[fm], b2);
                        mma8(acc[fm][3], af[fm], b3);
                    }
                }
            }

            __syncthreads();  // done with stage smem; overlay gates tile

            float (*gs)[68] = (float(*)[68])smem;
#pragma unroll
            for (int fm = 0; fm < 2; fm++) {
#pragma unroll
                for (int fn = 0; fn < 4; fn++) {
                    int m = wm + fm * 16 + lr;
                    int j = wn + fn * 8 + 2 * lc;
                    *(float2*)&gs[m][j]     = make_float2(acc[fm][fn][0], acc[fm][fn][1]);
                    *(float2*)&gs[m + 8][j] = make_float2(acc[fm][fn][2], acc[fm][fn][3]);
                }
            }
            __syncthreads();

            for (int q = tid; q < 128 * 16; q += NTHR) {
                int ml = q & 127, nl = q >> 7;
                float4 g4 = *(float4*)&gs[ml][nl * 4];
                float iv = g4.x + bias_s[nl * 4 + 0];
                float fv = g4.y + bias_s[nl * 4 + 1];
                float gv = g4.z + bias_s[nl * 4 + 2];
                float ov = g4.w + bias_s[nl * 4 + 3];
                int b = gm0 + ml, n = gn0 + nl;
                int idx = b * HID + n;
                float cold = g_c[idx];
                float cn = sigf(fv) * cold + sigf(iv) * tanhf(gv);
                float hn = sigf(ov) * tanhf(cn);
                g_c[idx] = cn;
                hnext[idx] = round_tf32(hn);
                out[(long)(b * T_feat + s) * HID + n] = hn;
            }
        }
        gsync(&sense);
    }

    gsync(&sense);  // total barriers even -> g_flag restored to 0
}

// ---------------- launcher ----------------
extern "C" void kernel_launch(void* const* d_in, const int* in_sizes, int n_in,
                              void* d_out, int out_size)
{
    int base = 2;
    if (n_in >= 11 && in_sizes[2] == 1) base = 3;

    const float* dh     = (const float*)d_in[0];
    const int*   caps   = (const int*)d_in[1];
    const float* W_attn = (const float*)d_in[base + 0];
    const float* U_attn = (const float*)d_in[base + 1];
    const float* b_attn = (const float*)d_in[base + 2];
    const float* w_attn = (const float*)d_in[base + 3];
    const float* W_ih   = (const float*)d_in[base + 4];
    const float* W_hh   = (const float*)d_in[base + 5];
    const float* b_ih   = (const float*)d_in[base + 6];
    const float* b_hh   = (const float*)d_in[base + 7];
    float* out = (float*)d_out;

    const int T_feat = out_size / (BATCH * HID);  // 28

    static int configured = 0;
    if (!configured) {
        cudaFuncSetAttribute(recon_kernel, cudaFuncAttributeMaxDynamicSharedMemorySize,
                             GK_SMEM_BYTES);
        configured = 1;
    }

    recon_kernel<<<NBLK, NTHR, GK_SMEM_BYTES>>>(
        dh, caps, W_attn, U_attn, b_attn, w_attn,
        W_ih, W_hh, b_ih, b_hh, out, T_feat);
}

// round 6
// speedup vs baseline: 1.7380x; 1.1163x over previous
#include <cuda_runtime.h>
#include <cstdint>

#define T_CAP 64
#define BATCH 256
#define DEC   1024
#define HID   1024
#define ATTN  128
#define NBLK  128
#define NTHR  512

// ---------------- persistent scratch ----------------
__device__ float g_Uv[BATCH * T_CAP * ATTN];   // 8 MB, [b][t][a]
__device__ float g_h[2][BATCH * HID];          // double-buffered hidden (tf32-rounded)
__device__ float g_c[BATCH * HID];             // cell state (block-private tiles)
__device__ float g_ctx[BATCH * DEC];           // per-step context (tf32-rounded)
__device__ float g_Wih_r[4 * HID * DEC];       // tf32-rounded W_ih
__device__ float g_Whh_r[4 * HID * HID];       // tf32-rounded W_hh
__device__ int   g_cnt;
__device__ volatile int g_flag;

// ---------------- helpers ----------------
__device__ __forceinline__ uint32_t f2tf(float f) {
    uint32_t u;
    asm("cvt.rna.tf32.f32 %0, %1;" : "=r"(u) : "f"(f));
    return u;
}
__device__ __forceinline__ float round_tf32(float f) { return __uint_as_float(f2tf(f)); }

__device__ __forceinline__ void mma8(float* c, const uint32_t* a, const uint32_t* b) {
    asm volatile(
        "mma.sync.aligned.m16n8k8.row.col.f32.tf32.tf32.f32 "
        "{%0,%1,%2,%3}, {%4,%5,%6,%7}, {%8,%9}, {%0,%1,%2,%3};\n"
        : "+f"(c[0]), "+f"(c[1]), "+f"(c[2]), "+f"(c[3])
        : "r"(a[0]), "r"(a[1]), "r"(a[2]), "r"(a[3]),
          "r"(b[0]), "r"(b[1]));
}

__device__ __forceinline__ void ldsm4(uint32_t* r, uint32_t addr) {
    asm volatile("ldmatrix.sync.aligned.m8n8.x4.shared.b16 {%0,%1,%2,%3}, [%4];"
                 : "=r"(r[0]), "=r"(r[1]), "=r"(r[2]), "=r"(r[3]) : "r"(addr));
}

__device__ __forceinline__ uint32_t smem_u32(const void* p) {
    return (uint32_t)__cvta_generic_to_shared(p);
}
__device__ __forceinline__ void cp16(void* s, const float* g) {
    asm volatile("cp.async.ca.shared.global [%0], [%1], 16;\n" :: "r"(smem_u32(s)), "l"(g));
}
__device__ __forceinline__ void cp16cg(void* s, const float* g) {
    asm volatile("cp.async.cg.shared.global [%0], [%1], 16;\n" :: "r"(smem_u32(s)), "l"(g));
}
#define CP_COMMIT() asm volatile("cp.async.commit_group;\n" ::)
#define CP_WAIT(n)  asm volatile("cp.async.wait_group " #n ";\n" ::)

__device__ __forceinline__ float sigf(float x) { return 1.0f / (1.0f + __expf(-x)); }
__device__ __forceinline__ float tanh_fast(float x) {
    return __fdividef(2.0f, 1.0f + __expf(-2.0f * x)) - 1.0f;
}

#define SWZ(x) ((x) ^ (((x) >> 3) & 0x70))

// grid barrier (all NBLK blocks co-resident)
__device__ __forceinline__ void gsync(int* sense) {
    __syncthreads();
    int s = *sense ^ 1;
    *sense = s;
    if (threadIdx.x == 0) {
        __threadfence();
        if (atomicAdd(&g_cnt, 1) == NBLK - 1) {
            g_cnt = 0;
            __threadfence();
            g_flag = s;
        } else {
            while (g_flag != s) __nanosleep(32);
        }
        __threadfence();
    }
    __syncthreads();
}

// ---------------- Uv tile: 128(m) x 64(n) x 1024(k), one-time (warps 0-7 compute) ----------------
__device__ __forceinline__ void uv_tile(
    float* smem, const float* __restrict__ dh, const float* __restrict__ U_attn,
    const float* __restrict__ b_attn, int m0, int n0)
{
    float (*As)[128][20] = (float(*)[128][20])smem;
    float (*Bs)[64][20]  = (float(*)[64][20])(smem + 5120);

    const int tid = threadIdx.x;
    const int warp = tid >> 5, lane = tid & 31;
    const int am = (tid & 255) >> 1, ak = (tid & 1) * 8;
    const int bj = (tid & 255) >> 2, bk = (tid & 3) * 4;
    const int r = m0 + am;
    const long abase = ((long)((r & 63) * 256 + (r >> 6))) * 1024;
    const long bbase = (long)(n0 + bj) * 1024;
    const bool ldr = tid < 256;

    const int wm = (warp >> 2) * 64, wn = (warp & 3) * 16;
    const int lr = lane >> 2, lc = lane & 3;

    float acc[4][2][4];
#pragma unroll
    for (int i = 0; i < 4; i++)
#pragma unroll
        for (int j = 0; j < 2; j++)
#pragma unroll
            for (int k = 0; k < 4; k++) acc[i][j][k] = 0.0f;

    const int NS = 64;
    if (ldr) {
        cp16(&As[0][am][ak],     dh + abase + ak);
        cp16(&As[0][am][ak + 4], dh + abase + ak + 4);
        cp16(&Bs[0][bj][bk],     U_attn + bbase + bk);
    }
    CP_COMMIT();

    for (int s = 0; s < NS; s++) {
        if (s + 1 < NS) {
            int buf = (s + 1) & 1, k0 = (s + 1) * 16;
            if (ldr) {
                cp16(&As[buf][am][ak],     dh + abase + k0 + ak);
                cp16(&As[buf][am][ak + 4], dh + abase + k0 + ak + 4);
                cp16(&Bs[buf][bj][bk],     U_attn + bbase + k0 + bk);
            }
            CP_COMMIT();
            CP_WAIT(1);
        } else {
            CP_WAIT(0);
        }
        __syncthreads();
        if (warp < 8) {
            const int buf = s & 1;
#pragma unroll
            for (int kk = 0; kk < 16; kk += 8) {
                uint32_t af[4][4], bf[2][2];
#pragma unroll
                for (int fm = 0; fm < 4; fm++) {
                    int rr = wm + fm * 16 + lr;
                    af[fm][0] = f2tf(As[buf][rr][kk + lc]);
                    af[fm][1] = f2tf(As[buf][rr + 8][kk + lc]);
                    af[fm][2] = f2tf(As[buf][rr][kk + lc + 4]);
                    af[fm][3] = f2tf(As[buf][rr + 8][kk + lc + 4]);
                }
#pragma unroll
                for (int fn = 0; fn < 2; fn++) {
                    int jc = wn + fn * 8 + lr;
                    bf[fn][0] = f2tf(Bs[buf][jc][kk + lc]);
                    bf[fn][1] = f2tf(Bs[buf][jc][kk + lc + 4]);
                }
#pragma unroll
                for (int fm = 0; fm < 4; fm++)
#pragma unroll
                    for (int fn = 0; fn < 2; fn++) mma8(acc[fm][fn], af[fm], bf[fn]);
            }
        }
        __syncthreads();
    }

    if (warp < 8) {
#pragma unroll
        for (int fm = 0; fm < 4; fm++) {
#pragma unroll
            for (int fn = 0; fn < 2; fn++) {
                int rr = m0 + wm + fm * 16 + lr;
                int a  = n0 + wn + fn * 8 + 2 * lc;
                float ba0 = b_attn[a], ba1 = b_attn[a + 1];
                float2 v0 = make_float2(acc[fm][fn][0] + ba0, acc[fm][fn][1] + ba1);
                float2 v1 = make_float2(acc[fm][fn][2] + ba0, acc[fm][fn][3] + ba1);
                *(float2*)&g_Uv[rr * ATTN + a]       = v0;
                *(float2*)&g_Uv[(rr + 8) * ATTN + a] = v1;
            }
        }
    }
}

// smem (dynamic, bytes): A stages 8 x 16KB = 128KB ; B stages 8 x 8KB = 64KB
#define SM_A(sl)  ((sl) * 16384)
#define SM_B(sl)  (131072 + (sl) * 8192)
#define GK_SMEM_BYTES 196608

// ---------------- the persistent kernel ----------------
__global__ __launch_bounds__(NTHR, 1) void recon_kernel(
    const float* __restrict__ dh, const int* __restrict__ caps,
    const float* __restrict__ W_attn, const float* __restrict__ U_attn,
    const float* __restrict__ b_attn, const float* __restrict__ w_attn,
    const float* __restrict__ W_ih, const float* __restrict__ W_hh,
    const float* __restrict__ b_ih, const float* __restrict__ b_hh,
    float* __restrict__ out, int T_feat)
{
    extern __shared__ __align__(1024) float smem[];
    __shared__ float bias_s[64];

    const int tid = threadIdx.x, blk = blockIdx.x;
    const int warp = tid >> 5, lane = tid & 31;
    int sense = 0;

    const int gm0 = (blk & 1) * 128;
    const int gn0 = (blk >> 1) * 16;

    char* smem_c = (char*)smem;
    const uint32_t smem_base = smem_u32(smem);

    if (tid < 64) {
        int row = (tid & 3) * 1024 + gn0 + (tid >> 2);
        bias_s[tid] = b_ih[row] + b_hh[row];
    }

    // ---- phase 0: zero h/c, round weights, compute Uv ----
    for (int i = blk * NTHR + tid; i < BATCH * HID; i += NBLK * NTHR) {
        g_h[0][i] = 0.0f;
        g_c[i]    = 0.0f;
    }
    for (int i = blk * NTHR + tid; i < 4 * HID * DEC; i += NBLK * NTHR)
        g_Wih_r[i] = round_tf32(W_ih[i]);
    for (int i = blk * NTHR + tid; i < 4 * HID * HID; i += NBLK * NTHR)
        g_Whh_r[i] = round_tf32(W_hh[i]);
    for (int tix = blk; tix < 256; tix += NBLK)
        uv_tile(smem, dh, U_attn, b_attn, (tix & 127) * 128, (tix >> 7) * 64);
    gsync(&sense);

    // ---- gates loader indices: A 128rows x 32k (16KB), B 64j x 32k (8KB) ----
    const int a_row = tid >> 2, a_kf = (tid & 3) * 8;      // 2x16B per thread
    const int b_row = tid >> 3, b_kf = (tid & 7) * 4;      // 1x16B per thread
    const long a_goff = (long)(gm0 + a_row) * 1024 + a_kf;
    const long b_goff = (long)((b_row & 3) * 1024 + gn0 + (b_row >> 2)) * 1024 + b_kf;
    const int a_so = a_row * 128 + a_kf * 4;
    const int b_so = b_row * 128 + b_kf * 4;

    // ---- ldmatrix mapping: 16 warps = 4m x 4j; warp tile 32m x 16j ----
    const int wm = (warp & 3) * 32;
    const int wn = (warp >> 2) * 16;
    const int ls_row = ((lane >> 3) & 1) * 8 + (lane & 7);
    const int ls_colb = (lane >> 4) * 16;
    const uint32_t a_swz = SWZ((uint32_t)((wm + ls_row) * 128 + ls_colb));
    const uint32_t b_swz = SWZ((uint32_t)((wn + ls_row) * 128 + ls_colb));
    const int lr = lane >> 2, lc = lane & 3;

    for (int s = 0; s < T_feat; s++) {
        const float* hprev = g_h[s & 1];
        float* hnext = g_h[(s + 1) & 1];

        // ================= attention: 2 batch rows per block, 16 warps =================
        {
            const int b0 = blk * 2;
            float* hs  = smem;           // [2][1024]
            float* whs = smem + 2048;    // [2][128]
            float* wa  = smem + 2304;    // [128]
            float* es  = smem + 2432;    // [2][64]
            float* ps  = smem + 2560;    // [2][64]

            for (int i = tid; i < 2 * HID; i += NTHR)
                hs[i] = __ldcg(&hprev[b0 * HID + i]);
            if (tid < ATTN) wa[tid] = w_attn[tid];
            __syncthreads();

            // Wh: warp w owns 8 a-cols
            const float4* h0v = (const float4*)hs;
            const float4* h1v = (const float4*)(hs + 1024);
#pragma unroll
            for (int rr = 0; rr < 8; rr++) {
                int a = warp * 8 + rr;
                const float4* wrow = (const float4*)(W_attn + a * 1024);
                float d0 = 0.f, d1 = 0.f;
#pragma unroll
                for (int j = 0; j < 8; j++) {
                    float4 w4 = wrow[lane + 32 * j];
                    float4 x4 = h0v[lane + 32 * j];
                    float4 y4 = h1v[lane + 32 * j];
                    d0 += w4.x * x4.x + w4.y * x4.y + w4.z * x4.z + w4.w * x4.w;
                    d1 += w4.x * y4.x + w4.y * y4.y + w4.z * y4.z + w4.w * y4.w;
                }
#pragma unroll
                for (int off = 16; off; off >>= 1) {
                    d0 += __shfl_xor_sync(0xffffffffu, d0, off);
                    d1 += __shfl_xor_sync(0xffffffffu, d1, off);
                }
                if (lane == 0) { whs[a] = d0; whs[128 + a] = d1; }
            }
            __syncthreads();

            // energies: 4 t per warp
            for (int t = warp; t < T_CAP; t += 16) {
#pragma unroll
                for (int bi = 0; bi < 2; bi++) {
                    const float* uv = g_Uv + ((long)(b0 + bi) * T_CAP + t) * ATTN;
                    float sE = 0.f;
#pragma unroll
                    for (int q = 0; q < 4; q++) {
                        int a = lane + q * 32;
                        sE += wa[a] * tanh_fast(whs[bi * 128 + a] + uv[a]);
                    }
#pragma unroll
                    for (int off = 16; off; off >>= 1)
                        sE += __shfl_xor_sync(0xffffffffu, sE, off);
                    if (lane == 0) {
                        int cp = caps[t * BATCH + b0 + bi];
                        es[bi * 64 + t] = (cp != 0 && cp != 2) ? sE : -1e30f;
                    }
                }
            }
            __syncthreads();

            if (warp < 2) {
                int bi = warp;
                float e0 = es[bi * 64 + lane], e1 = es[bi * 64 + lane + 32];
                float mx = fmaxf(e0, e1);
#pragma unroll
                for (int off = 16; off; off >>= 1)
                    mx = fmaxf(mx, __shfl_xor_sync(0xffffffffu, mx, off));
                float x0 = __expf(e0 - mx), x1 = __expf(e1 - mx);
                float sm = x0 + x1;
#pragma unroll
                for (int off = 16; off; off >>= 1)
                    sm += __shfl_xor_sync(0xffffffffu, sm, off);
                float inv = 1.0f / sm;
                ps[bi * 64 + lane]      = x0 * inv;
                ps[bi * 64 + lane + 32] = x1 * inv;
            }
            __syncthreads();

            // ctx: thread owns (row = tid>>8, 4 consecutive d)
            {
                const int row = tid >> 8;
                const int d = (tid & 255) * 4;
                float4 a0 = make_float4(0.f, 0.f, 0.f, 0.f);
                const float* pr = ps + row * 64;
#pragma unroll 4
                for (int t = 0; t < T_CAP; t++) {
                    float p = pr[t];
                    float4 x = *(const float4*)&dh[(long)(t * BATCH + b0 + row) * DEC + d];
                    a0.x += p * x.x; a0.y += p * x.y; a0.z += p * x.z; a0.w += p * x.w;
                }
                a0.x = round_tf32(a0.x); a0.y = round_tf32(a0.y);
                a0.z = round_tf32(a0.z); a0.w = round_tf32(a0.w);
                *(float4*)&g_ctx[(long)(b0 + row) * DEC + d] = a0;
            }
        }
        gsync(&sense);

        // ===== gates: 128(m) x 64(j) x 2048(k); 8-stage ring, distance 6 =====
        {
            const int NS = 64;  // BK=32

            auto load_stage = [&](int ks) {
                int sl = ks & 7;
                int k0 = ks * 32;
                int kb = k0 & 1023;
                const float* Asrc = ((k0 < 1024) ? g_ctx : hprev) + a_goff + kb;
                const float* Bsrc = ((k0 < 1024) ? g_Wih_r : g_Whh_r) + b_goff + kb;
                char* Ab = smem_c + SM_A(sl);
                char* Bb = smem_c + SM_B(sl);
                cp16cg(Ab + SWZ(a_so),      Asrc);
                cp16cg(Ab + SWZ(a_so + 16), Asrc + 4);
                cp16(Bb + SWZ(b_so), Bsrc);
                CP_COMMIT();
            };

            float acc[2][2][4];
#pragma unroll
            for (int i = 0; i < 2; i++)
#pragma unroll
                for (int j = 0; j < 2; j++)
#pragma unroll
                    for (int k = 0; k < 4; k++) acc[i][j][k] = 0.0f;

#pragma unroll
            for (int p = 0; p < 6; p++) load_stage(p);

            for (int ks = 0; ks < NS; ks++) {
                if (ks + 6 < NS) {
                    load_stage(ks + 6);
                    CP_WAIT(6);
                } else {
                    int rem = NS - 1 - ks;
                    if (rem >= 5)      { CP_WAIT(5); }
                    else if (rem == 4) { CP_WAIT(4); }
                    else if (rem == 3) { CP_WAIT(3); }
                    else if (rem == 2) { CP_WAIT(2); }
                    else if (rem == 1) { CP_WAIT(1); }
                    else               { CP_WAIT(0); }
                }
                __syncthreads();

                const int sl = ks & 7;
                const uint32_t Ab = smem_base + SM_A(sl);
                const uint32_t Bb = smem_base + SM_B(sl);
#pragma unroll
                for (int kk = 0; kk < 4; kk++) {
                    const uint32_t kofs = (uint32_t)(kk * 32);
                    uint32_t af0[4], af1[4], bf[4];
                    ldsm4(af0, Ab + (a_swz ^ kofs));
                    ldsm4(af1, Ab + 2048 + (a_swz ^ kofs));
                    ldsm4(bf,  Bb + (b_swz ^ kofs));
                    uint32_t b0[2] = {bf[0], bf[2]};
                    uint32_t b1[2] = {bf[1], bf[3]};
                    mma8(acc[0][0], af0, b0);
                    mma8(acc[0][1], af0, b1);
                    mma8(acc[1][0], af1, b0);
                    mma8(acc[1][1], af1, b1);
                }
            }

            __syncthreads();  // stage smem dead; overlay gates tile

            float (*gs)[68] = (float(*)[68])smem;
#pragma unroll
            for (int fm = 0; fm < 2; fm++) {
#pragma unroll
                for (int fn = 0; fn < 2; fn++) {
                    int m = wm + fm * 16 + lr;
                    int j = wn + fn * 8 + 2 * lc;
                    *(float2*)&gs[m][j]     = make_float2(acc[fm][fn][0], acc[fm][fn][1]);
                    *(float2*)&gs[m + 8][j] = make_float2(acc[fm][fn][2], acc[fm][fn][3]);
                }
            }
            __syncthreads();

            for (int q = tid; q < 128 * 16; q += NTHR) {
                int ml = q & 127, nl = q >> 7;
                float4 g4 = *(float4*)&gs[ml][nl * 4];
                float iv = g4.x + bias_s[nl * 4 + 0];
                float fv = g4.y + bias_s[nl * 4 + 1];
                float gv = g4.z + bias_s[nl * 4 + 2];
                float ov = g4.w + bias_s[nl * 4 + 3];
                int b = gm0 + ml, n = gn0 + nl;
                int idx = b * HID + n;
                float cold = g_c[idx];
                float cn = sigf(fv) * cold + sigf(iv) * tanhf(gv);
                float hn = sigf(ov) * tanhf(cn);
                g_c[idx] = cn;
                hnext[idx] = round_tf32(hn);
                out[(long)(b * T_feat + s) * HID + n] = hn;
            }
        }
        gsync(&sense);
    }

    gsync(&sense);  // total barriers even -> g_flag restored to 0
}

// ---------------- launcher ----------------
extern "C" void kernel_launch(void* const* d_in, const int* in_sizes, int n_in,
                              void* d_out, int out_size)
{
    int base = 2;
    if (n_in >= 11 && in_sizes[2] == 1) base = 3;

    const float* dh     = (const float*)d_in[0];
    const int*   caps   = (const int*)d_in[1];
    const float* W_attn = (const float*)d_in[base + 0];
    const float* U_attn = (const float*)d_in[base + 1];
    const float* b_attn = (const float*)d_in[base + 2];
    const float* w_attn = (const float*)d_in[base + 3];
    const float* W_ih   = (const float*)d_in[base + 4];
    const float* W_hh   = (const float*)d_in[base + 5];
    const float* b_ih   = (const float*)d_in[base + 6];
    const float* b_hh   = (const float*)d_in[base + 7];
    float* out = (float*)d_out;

    const int T_feat = out_size / (BATCH * HID);  // 28

    static int configured = 0;
    if (!configured) {
        cudaFuncSetAttribute(recon_kernel, cudaFuncAttributeMaxDynamicSharedMemorySize,
                             GK_SMEM_BYTES);
        configured = 1;
    }

    recon_kernel<<<NBLK, NTHR, GK_SMEM_BYTES>>>(
        dh, caps, W_attn, U_attn, b_attn, w_attn,
        W_ih, W_hh, b_ih, b_hh, out, T_feat);
}

// round 7
// speedup vs baseline: 2.4874x; 1.4312x over previous
#include <cuda_runtime.h>
#include <cuda_fp16.h>
#include <cstdint>

#define T_CAP 64
#define BATCH 256
#define DEC   1024
#define HID   1024
#define ATTN  128
#define NBLK  128
#define NTHR  512

// ---------------- persistent scratch ----------------
__device__ float  g_Uv[BATCH * T_CAP * ATTN];   // 8 MB, [b][t][a]
__device__ float  g_h[2][BATCH * HID];          // fp32 hidden (attention)
__device__ __half g_h_h[2][BATCH * HID];        // fp16 hidden (gates GEMM)
__device__ float  g_c[BATCH * HID];             // cell state (block-private tiles)
__device__ __half g_ctx_h[BATCH * DEC];         // fp16 context (gates GEMM)
__device__ __half g_Wih_h[4 * HID * DEC];       // fp16 W_ih (8 MB)
__device__ __half g_Whh_h[4 * HID * HID];       // fp16 W_hh (8 MB)
__device__ int    g_cnt;
__device__ volatile int g_flag;

// ---------------- helpers ----------------
__device__ __forceinline__ uint32_t f2tf(float f) {
    uint32_t u;
    asm("cvt.rna.tf32.f32 %0, %1;" : "=r"(u) : "f"(f));
    return u;
}

__device__ __forceinline__ void mma8(float* c, const uint32_t* a, const uint32_t* b) {
    asm volatile(
        "mma.sync.aligned.m16n8k8.row.col.f32.tf32.tf32.f32 "
        "{%0,%1,%2,%3}, {%4,%5,%6,%7}, {%8,%9}, {%0,%1,%2,%3};\n"
        : "+f"(c[0]), "+f"(c[1]), "+f"(c[2]), "+f"(c[3])
        : "r"(a[0]), "r"(a[1]), "r"(a[2]), "r"(a[3]),
          "r"(b[0]), "r"(b[1]));
}

__device__ __forceinline__ void mma16(float* c, const uint32_t* a, const uint32_t* b) {
    asm volatile(
        "mma.sync.aligned.m16n8k16.row.col.f32.f16.f16.f32 "
        "{%0,%1,%2,%3}, {%4,%5,%6,%7}, {%8,%9}, {%0,%1,%2,%3};\n"
        : "+f"(c[0]), "+f"(c[1]), "+f"(c[2]), "+f"(c[3])
        : "r"(a[0]), "r"(a[1]), "r"(a[2]), "r"(a[3]),
          "r"(b[0]), "r"(b[1]));
}

__device__ __forceinline__ void ldsm4(uint32_t* r, uint32_t addr) {
    asm volatile("ldmatrix.sync.aligned.m8n8.x4.shared.b16 {%0,%1,%2,%3}, [%4];"
                 : "=r"(r[0]), "=r"(r[1]), "=r"(r[2]), "=r"(r[3]) : "r"(addr));
}

__device__ __forceinline__ uint32_t smem_u32(const void* p) {
    return (uint32_t)__cvta_generic_to_shared(p);
}
__device__ __forceinline__ void cp16(void* s, const void* g) {
    asm volatile("cp.async.ca.shared.global [%0], [%1], 16;\n" :: "r"(smem_u32(s)), "l"(g));
}
__device__ __forceinline__ void cp16cg(void* s, const void* g) {
    asm volatile("cp.async.cg.shared.global [%0], [%1], 16;\n" :: "r"(smem_u32(s)), "l"(g));
}
#define CP_COMMIT() asm volatile("cp.async.commit_group;\n" ::)
#define CP_WAIT(n)  asm volatile("cp.async.wait_group " #n ";\n" ::)

__device__ __forceinline__ float sigf(float x) { return 1.0f / (1.0f + __expf(-x)); }
__device__ __forceinline__ float tanh_fast(float x) {
    return __fdividef(2.0f, 1.0f + __expf(-2.0f * x)) - 1.0f;
}

#define SWZ(x) ((x) ^ (((x) >> 3) & 0x70))

// grid barrier (all NBLK blocks co-resident)
__device__ __forceinline__ void gsync(int* sense) {
    __syncthreads();
    int s = *sense ^ 1;
    *sense = s;
    if (threadIdx.x == 0) {
        __threadfence();
        if (atomicAdd(&g_cnt, 1) == NBLK - 1) {
            g_cnt = 0;
            __threadfence();
            g_flag = s;
        } else {
            while (g_flag != s) __nanosleep(32);
        }
        __threadfence();
    }
    __syncthreads();
}

// ---------------- Uv tile: 128(m) x 64(n) x 1024(k), one-time ----------------
__device__ __forceinline__ void uv_tile(
    float* smem, const float* __restrict__ dh, const float* __restrict__ U_attn,
    const float* __restrict__ b_attn, int m0, int n0)
{
    float (*As)[128][20] = (float(*)[128][20])smem;
    float (*Bs)[64][20]  = (float(*)[64][20])(smem + 5120);

    const int tid = threadIdx.x;
    const int warp = tid >> 5, lane = tid & 31;
    const int am = (tid & 255) >> 1, ak = (tid & 1) * 8;
    const int bj = (tid & 255) >> 2, bk = (tid & 3) * 4;
    const int r = m0 + am;
    const long abase = ((long)((r & 63) * 256 + (r >> 6))) * 1024;
    const long bbase = (long)(n0 + bj) * 1024;
    const bool ldr = tid < 256;

    const int wm = (warp >> 2) * 64, wn = (warp & 3) * 16;
    const int lr = lane >> 2, lc = lane & 3;

    float acc[4][2][4];
#pragma unroll
    for (int i = 0; i < 4; i++)
#pragma unroll
        for (int j = 0; j < 2; j++)
#pragma unroll
            for (int k = 0; k < 4; k++) acc[i][j][k] = 0.0f;

    const int NS = 64;
    if (ldr) {
        cp16(&As[0][am][ak],     dh + abase + ak);
        cp16(&As[0][am][ak + 4], dh + abase + ak + 4);
        cp16(&Bs[0][bj][bk],     U_attn + bbase + bk);
    }
    CP_COMMIT();

    for (int s = 0; s < NS; s++) {
        if (s + 1 < NS) {
            int buf = (s + 1) & 1, k0 = (s + 1) * 16;
            if (ldr) {
                cp16(&As[buf][am][ak],     dh + abase + k0 + ak);
                cp16(&As[buf][am][ak + 4], dh + abase + k0 + ak + 4);
                cp16(&Bs[buf][bj][bk],     U_attn + bbase + k0 + bk);
            }
            CP_COMMIT();
            CP_WAIT(1);
        } else {
            CP_WAIT(0);
        }
        __syncthreads();
        if (warp < 8) {
            const int buf = s & 1;
#pragma unroll
            for (int kk = 0; kk < 16; kk += 8) {
                uint32_t af[4][4], bf[2][2];
#pragma unroll
                for (int fm = 0; fm < 4; fm++) {
                    int rr = wm + fm * 16 + lr;
                    af[fm][0] = f2tf(As[buf][rr][kk + lc]);
                    af[fm][1] = f2tf(As[buf][rr + 8][kk + lc]);
                    af[fm][2] = f2tf(As[buf][rr][kk + lc + 4]);
                    af[fm][3] = f2tf(As[buf][rr + 8][kk + lc + 4]);
                }
#pragma unroll
                for (int fn = 0; fn < 2; fn++) {
                    int jc = wn + fn * 8 + lr;
                    bf[fn][0] = f2tf(Bs[buf][jc][kk + lc]);
                    bf[fn][1] = f2tf(Bs[buf][jc][kk + lc + 4]);
                }
#pragma unroll
                for (int fm = 0; fm < 4; fm++)
#pragma unroll
                    for (int fn = 0; fn < 2; fn++) mma8(acc[fm][fn], af[fm], bf[fn]);
            }
        }
        __syncthreads();
    }

    if (warp < 8) {
#pragma unroll
        for (int fm = 0; fm < 4; fm++) {
#pragma unroll
            for (int fn = 0; fn < 2; fn++) {
                int rr = m0 + wm + fm * 16 + lr;
                int a  = n0 + wn + fn * 8 + 2 * lc;
                float ba0 = b_attn[a], ba1 = b_attn[a + 1];
                float2 v0 = make_float2(acc[fm][fn][0] + ba0, acc[fm][fn][1] + ba1);
                float2 v1 = make_float2(acc[fm][fn][2] + ba0, acc[fm][fn][3] + ba1);
                *(float2*)&g_Uv[rr * ATTN + a]       = v0;
                *(float2*)&g_Uv[(rr + 8) * ATTN + a] = v1;
            }
        }
    }
}

// smem (bytes): A stages 8 x 16KB = 128KB ; B stages 8 x 8KB = 64KB
#define SM_A(sl)  ((sl) * 16384)
#define SM_B(sl)  (131072 + (sl) * 8192)
#define GK_SMEM_BYTES 196608

// ---------------- the persistent kernel ----------------
__global__ __launch_bounds__(NTHR, 1) void recon_kernel(
    const float* __restrict__ dh, const int* __restrict__ caps,
    const float* __restrict__ W_attn, const float* __restrict__ U_attn,
    const float* __restrict__ b_attn, const float* __restrict__ w_attn,
    const float* __restrict__ W_ih, const float* __restrict__ W_hh,
    const float* __restrict__ b_ih, const float* __restrict__ b_hh,
    float* __restrict__ out, int T_feat)
{
    extern __shared__ __align__(1024) float smem[];
    __shared__ float bias_s[64];

    const int tid = threadIdx.x, blk = blockIdx.x;
    const int warp = tid >> 5, lane = tid & 31;
    int sense = 0;

    const int gm0 = (blk & 1) * 128;
    const int gn0 = (blk >> 1) * 16;

    char* smem_c = (char*)smem;
    const uint32_t smem_base = smem_u32(smem);

    if (tid < 64) {
        int row = (tid & 3) * 1024 + gn0 + (tid >> 2);
        bias_s[tid] = b_ih[row] + b_hh[row];
    }

    // ---- phase 0: zero h/c, convert weights to fp16, compute Uv ----
    for (int i = blk * NTHR + tid; i < BATCH * HID; i += NBLK * NTHR) {
        g_h[0][i]   = 0.0f;
        g_h_h[0][i] = __float2half_rn(0.0f);
        g_c[i]      = 0.0f;
    }
    for (int i = blk * NTHR + tid; i < 4 * HID * DEC; i += NBLK * NTHR)
        g_Wih_h[i] = __float2half_rn(W_ih[i]);
    for (int i = blk * NTHR + tid; i < 4 * HID * HID; i += NBLK * NTHR)
        g_Whh_h[i] = __float2half_rn(W_hh[i]);
    for (int tix = blk; tix < 256; tix += NBLK)
        uv_tile(smem, dh, U_attn, b_attn, (tix & 127) * 128, (tix >> 7) * 64);
    gsync(&sense);

    // ---- gates loaders: A 128 rows x 64k fp16 (16KB), B 64 j x 64k fp16 (8KB) ----
    const int a_row = tid >> 2;
    const int a_c   = (tid & 3) * 16;                  // half offset within 64
    const long a_goff = (long)(gm0 + a_row) * 1024 + a_c;
    const int a_so  = a_row * 128 + a_c * 2;           // smem bytes
    const int b_row = tid >> 3;
    const int b_c   = (tid & 7) * 8;
    const long b_goff = (long)((b_row & 3) * 1024 + gn0 + (b_row >> 2)) * 1024 + b_c;
    const int b_so  = b_row * 128 + b_c * 2;

    // ---- ldmatrix mapping: 16 warps = 4m x 4j; warp tile 32m x 16j ----
    const int wm = (warp & 3) * 32;
    const int wn = (warp >> 2) * 16;
    const int ls_row = ((lane >> 3) & 1) * 8 + (lane & 7);
    const int ls_colb = (lane >> 4) * 16;
    const uint32_t a_swz = SWZ((uint32_t)((wm + ls_row) * 128 + ls_colb));
    const uint32_t b_swz = SWZ((uint32_t)((wn + ls_row) * 128 + ls_colb));
    const int lr = lane >> 2, lc = lane & 3;

    for (int s = 0; s < T_feat; s++) {
        const float*  hprev   = g_h[s & 1];
        const __half* hprev_h = g_h_h[s & 1];
        float*  hnext   = g_h[(s + 1) & 1];
        __half* hnext_h = g_h_h[(s + 1) & 1];

        // ================= attention: 2 batch rows per block =================
        {
            const int b0 = blk * 2;
            float* hs  = smem;           // [2][1024]
            float* whs = smem + 2048;    // [2][128]
            float* wa  = smem + 2304;    // [128]
            float* es  = smem + 2432;    // [2][64]
            float* ps  = smem + 2560;    // [2][64]

            for (int i = tid; i < 2 * HID; i += NTHR)
                hs[i] = __ldcg(&hprev[b0 * HID + i]);
            if (tid < ATTN) wa[tid] = w_attn[tid];
            __syncthreads();

            const float4* h0v = (const float4*)hs;
            const float4* h1v = (const float4*)(hs + 1024);
#pragma unroll
            for (int rr = 0; rr < 8; rr++) {
                int a = warp * 8 + rr;
                const float4* wrow = (const float4*)(W_attn + a * 1024);
                float d0 = 0.f, d1 = 0.f;
#pragma unroll
                for (int j = 0; j < 8; j++) {
                    float4 w4 = wrow[lane + 32 * j];
                    float4 x4 = h0v[lane + 32 * j];
                    float4 y4 = h1v[lane + 32 * j];
                    d0 += w4.x * x4.x + w4.y * x4.y + w4.z * x4.z + w4.w * x4.w;
                    d1 += w4.x * y4.x + w4.y * y4.y + w4.z * y4.z + w4.w * y4.w;
                }
#pragma unroll
                for (int off = 16; off; off >>= 1) {
                    d0 += __shfl_xor_sync(0xffffffffu, d0, off);
                    d1 += __shfl_xor_sync(0xffffffffu, d1, off);
                }
                if (lane == 0) { whs[a] = d0; whs[128 + a] = d1; }
            }
            __syncthreads();

            for (int t = warp; t < T_CAP; t += 16) {
#pragma unroll
                for (int bi = 0; bi < 2; bi++) {
                    const float* uv = g_Uv + ((long)(b0 + bi) * T_CAP + t) * ATTN;
                    float sE = 0.f;
#pragma unroll
                    for (int q = 0; q < 4; q++) {
                        int a = lane + q * 32;
                        sE += wa[a] * tanh_fast(whs[bi * 128 + a] + uv[a]);
                    }
#pragma unroll
                    for (int off = 16; off; off >>= 1)
                        sE += __shfl_xor_sync(0xffffffffu, sE, off);
                    if (lane == 0) {
                        int cp = caps[t * BATCH + b0 + bi];
                        es[bi * 64 + t] = (cp != 0 && cp != 2) ? sE : -1e30f;
                    }
                }
            }
            __syncthreads();

            if (warp < 2) {
                int bi = warp;
                float e0 = es[bi * 64 + lane], e1 = es[bi * 64 + lane + 32];
                float mx = fmaxf(e0, e1);
#pragma unroll
                for (int off = 16; off; off >>= 1)
                    mx = fmaxf(mx, __shfl_xor_sync(0xffffffffu, mx, off));
                float x0 = __expf(e0 - mx), x1 = __expf(e1 - mx);
                float sm = x0 + x1;
#pragma unroll
                for (int off = 16; off; off >>= 1)
                    sm += __shfl_xor_sync(0xffffffffu, sm, off);
                float inv = 1.0f / sm;
                ps[bi * 64 + lane]      = x0 * inv;
                ps[bi * 64 + lane + 32] = x1 * inv;
            }
            __syncthreads();

            // ctx -> fp16
            {
                const int row = tid >> 8;
                const int d = (tid & 255) * 4;
                float4 a0 = make_float4(0.f, 0.f, 0.f, 0.f);
                const float* pr = ps + row * 64;
#pragma unroll 4
                for (int t = 0; t < T_CAP; t++) {
                    float p = pr[t];
                    float4 x = *(const float4*)&dh[(long)(t * BATCH + b0 + row) * DEC + d];
                    a0.x += p * x.x; a0.y += p * x.y; a0.z += p * x.z; a0.w += p * x.w;
                }
                __half2 lo = __floats2half2_rn(a0.x, a0.y);
                __half2 hi = __floats2half2_rn(a0.z, a0.w);
                uint2 pk;
                pk.x = *(uint32_t*)&lo;
                pk.y = *(uint32_t*)&hi;
                *(uint2*)&g_ctx_h[(long)(b0 + row) * DEC + d] = pk;
            }
        }
        gsync(&sense);

        // ===== gates: 128(m) x 64(j) x 2048(k) fp16 mma; BK=64, 8-stage ring =====
        {
            const int NS = 32;

            auto load_stage = [&](int ks) {
                int sl = ks & 7;
                int k0 = ks * 64;
                int kb = k0 & 1023;
                const __half* Asrc = ((k0 < 1024) ? g_ctx_h : hprev_h) + a_goff + kb;
                const __half* Bsrc = ((k0 < 1024) ? g_Wih_h : g_Whh_h) + b_goff + kb;
                char* Ab = smem_c + SM_A(sl);
                char* Bb = smem_c + SM_B(sl);
                cp16cg(Ab + SWZ(a_so),      Asrc);
                cp16cg(Ab + SWZ(a_so + 16), Asrc + 8);
                cp16(Bb + SWZ(b_so), Bsrc);
                CP_COMMIT();
            };

            float acc[2][2][4];
#pragma unroll
            for (int i = 0; i < 2; i++)
#pragma unroll
                for (int j = 0; j < 2; j++)
#pragma unroll
                    for (int k = 0; k < 4; k++) acc[i][j][k] = 0.0f;

#pragma unroll
            for (int p = 0; p < 6; p++) load_stage(p);

            for (int ks = 0; ks < NS; ks++) {
                if (ks + 6 < NS) {
                    load_stage(ks + 6);
                    CP_WAIT(6);
                } else {
                    int rem = NS - 1 - ks;
                    if (rem >= 5)      { CP_WAIT(5); }
                    else if (rem == 4) { CP_WAIT(4); }
                    else if (rem == 3) { CP_WAIT(3); }
                    else if (rem == 2) { CP_WAIT(2); }
                    else if (rem == 1) { CP_WAIT(1); }
                    else               { CP_WAIT(0); }
                }
                __syncthreads();

                const int sl = ks & 7;
                const uint32_t Ab = smem_base + SM_A(sl);
                const uint32_t Bb = smem_base + SM_B(sl);
#pragma unroll
                for (int kk = 0; kk < 4; kk++) {
                    const uint32_t kofs = (uint32_t)(kk * 32);
                    uint32_t af0[4], af1[4], bf[4];
                    ldsm4(af0, Ab + (a_swz ^ kofs));
                    ldsm4(af1, Ab + 2048 + (a_swz ^ kofs));
                    ldsm4(bf,  Bb + (b_swz ^ kofs));
                    uint32_t b0[2] = {bf[0], bf[2]};
                    uint32_t b1[2] = {bf[1], bf[3]};
                    mma16(acc[0][0], af0, b0);
                    mma16(acc[0][1], af0, b1);
                    mma16(acc[1][0], af1, b0);
                    mma16(acc[1][1], af1, b1);
                }
            }

            __syncthreads();  // stage smem dead; overlay gates tile

            float (*gs)[68] = (float(*)[68])smem;
#pragma unroll
            for (int fm = 0; fm < 2; fm++) {
#pragma unroll
                for (int fn = 0; fn < 2; fn++) {
                    int m = wm + fm * 16 + lr;
                    int j = wn + fn * 8 + 2 * lc;
                    *(float2*)&gs[m][j]     = make_float2(acc[fm][fn][0], acc[fm][fn][1]);
                    *(float2*)&gs[m + 8][j] = make_float2(acc[fm][fn][2], acc[fm][fn][3]);
                }
            }
            __syncthreads();

            for (int q = tid; q < 128 * 16; q += NTHR) {
                int ml = q & 127, nl = q >> 7;
                float4 g4 = *(float4*)&gs[ml][nl * 4];
                float iv = g4.x + bias_s[nl * 4 + 0];
                float fv = g4.y + bias_s[nl * 4 + 1];
                float gv = g4.z + bias_s[nl * 4 + 2];
                float ov = g4.w + bias_s[nl * 4 + 3];
                int b = gm0 + ml, n = gn0 + nl;
                int idx = b * HID + n;
                float cold = g_c[idx];
                float cn = sigf(fv) * cold + sigf(iv) * tanhf(gv);
                float hn = sigf(ov) * tanhf(cn);
                g_c[idx] = cn;
                hnext[idx]   = hn;
                hnext_h[idx] = __float2half_rn(hn);
                out[(long)(b * T_feat + s) * HID + n] = hn;
            }
        }
        gsync(&sense);
    }

    gsync(&sense);  // total barriers even -> g_flag restored to 0
}

// ---------------- launcher ----------------
extern "C" void kernel_launch(void* const* d_in, const int* in_sizes, int n_in,
                              void* d_out, int out_size)
{
    int base = 2;
    if (n_in >= 11 && in_sizes[2] == 1) base = 3;

    const float* dh     = (const float*)d_in[0];
    const int*   caps   = (const int*)d_in[1];
    const float* W_attn = (const float*)d_in[base + 0];
    const float* U_attn = (const float*)d_in[base + 1];
    const float* b_attn = (const float*)d_in[base + 2];
    const float* w_attn = (const float*)d_in[base + 3];
    const float* W_ih   = (const float*)d_in[base + 4];
    const float* W_hh   = (const float*)d_in[base + 5];
    const float* b_ih   = (const float*)d_in[base + 6];
    const float* b_hh   = (const float*)d_in[base + 7];
    float* out = (float*)d_out;

    const int T_feat = out_size / (BATCH * HID);  // 28

    static int configured = 0;
    if (!configured) {
        cudaFuncSetAttribute(recon_kernel, cudaFuncAttributeMaxDynamicSharedMemorySize,
                             GK_SMEM_BYTES);
        configured = 1;
    }

    recon_kernel<<<NBLK, NTHR, GK_SMEM_BYTES>>>(
        dh, caps, W_attn, U_attn, b_attn, w_attn,
        W_ih, W_hh, b_ih, b_hh, out, T_feat);
}

// round 8
// speedup vs baseline: 2.6026x; 1.0463x over previous
#include <cuda_runtime.h>
#include <cuda_fp16.h>
#include <cstdint>

#define T_CAP 64
#define BATCH 256
#define DEC   1024
#define HID   1024
#define ATTN  128
#define NBLK  128
#define NTHR  512

// ---------------- persistent scratch ----------------
__device__ float  g_Uv[BATCH * T_CAP * ATTN];   // 8 MB, [b][t][a]
__device__ float  g_h[2][BATCH * HID];          // fp32 hidden (attention)
__device__ __half g_h_h[2][BATCH * HID];        // fp16 hidden (gates GEMM)
__device__ float  g_c[BATCH * HID];             // cell state (block-private tiles)
__device__ __half g_ctx_h[BATCH * DEC];         // fp16 context (gates GEMM)
__device__ __half g_Wih_h[4 * HID * DEC];       // fp16 W_ih (8 MB)
__device__ __half g_Whh_h[4 * HID * HID];       // fp16 W_hh (8 MB)
__device__ int    g_cnt;
__device__ volatile int g_flag;

// ---------------- helpers ----------------
__device__ __forceinline__ uint32_t f2tf(float f) {
    uint32_t u;
    asm("cvt.rna.tf32.f32 %0, %1;" : "=r"(u) : "f"(f));
    return u;
}

__device__ __forceinline__ void mma8(float* c, const uint32_t* a, const uint32_t* b) {
    asm volatile(
        "mma.sync.aligned.m16n8k8.row.col.f32.tf32.tf32.f32 "
        "{%0,%1,%2,%3}, {%4,%5,%6,%7}, {%8,%9}, {%0,%1,%2,%3};\n"
        : "+f"(c[0]), "+f"(c[1]), "+f"(c[2]), "+f"(c[3])
        : "r"(a[0]), "r"(a[1]), "r"(a[2]), "r"(a[3]),
          "r"(b[0]), "r"(b[1]));
}

__device__ __forceinline__ void mma16(float* c, const uint32_t* a, const uint32_t* b) {
    asm volatile(
        "mma.sync.aligned.m16n8k16.row.col.f32.f16.f16.f32 "
        "{%0,%1,%2,%3}, {%4,%5,%6,%7}, {%8,%9}, {%0,%1,%2,%3};\n"
        : "+f"(c[0]), "+f"(c[1]), "+f"(c[2]), "+f"(c[3])
        : "r"(a[0]), "r"(a[1]), "r"(a[2]), "r"(a[3]),
          "r"(b[0]), "r"(b[1]));
}

__device__ __forceinline__ void ldsm4(uint32_t* r, uint32_t addr) {
    asm volatile("ldmatrix.sync.aligned.m8n8.x4.shared.b16 {%0,%1,%2,%3}, [%4];"
                 : "=r"(r[0]), "=r"(r[1]), "=r"(r[2]), "=r"(r[3]) : "r"(addr));
}

__device__ __forceinline__ uint32_t smem_u32(const void* p) {
    return (uint32_t)__cvta_generic_to_shared(p);
}
__device__ __forceinline__ void cp16(void* s, const void* g) {
    asm volatile("cp.async.ca.shared.global [%0], [%1], 16;\n" :: "r"(smem_u32(s)), "l"(g));
}
__device__ __forceinline__ void cp16cg(void* s, const void* g) {
    asm volatile("cp.async.cg.shared.global [%0], [%1], 16;\n" :: "r"(smem_u32(s)), "l"(g));
}
#define CP_COMMIT() asm volatile("cp.async.commit_group;\n" ::)
#define CP_WAIT(n)  asm volatile("cp.async.wait_group " #n ";\n" ::)

__device__ __forceinline__ float sigf(float x) { return 1.0f / (1.0f + __expf(-x)); }
__device__ __forceinline__ float tanh_fast(float x) {
    return __fdividef(2.0f, 1.0f + __expf(-2.0f * x)) - 1.0f;
}

#define SWZ(x) ((x) ^ (((x) >> 3) & 0x70))

// grid barrier (all NBLK blocks co-resident)
__device__ __forceinline__ void gsync(int* sense) {
    __syncthreads();
    int s = *sense ^ 1;
    *sense = s;
    if (threadIdx.x == 0) {
        __threadfence();
        if (atomicAdd(&g_cnt, 1) == NBLK - 1) {
            g_cnt = 0;
            __threadfence();
            g_flag = s;
        } else {
            while (g_flag != s) __nanosleep(32);
        }
        __threadfence();
    }
    __syncthreads();
}

// ---------------- Uv tile: 128(m) x 64(n) x 1024(k), one-time ----------------
__device__ __forceinline__ void uv_tile(
    float* smem, const float* __restrict__ dh, const float* __restrict__ U_attn,
    const float* __restrict__ b_attn, int m0, int n0)
{
    float (*As)[128][20] = (float(*)[128][20])smem;
    float (*Bs)[64][20]  = (float(*)[64][20])(smem + 5120);

    const int tid = threadIdx.x;
    const int warp = tid >> 5, lane = tid & 31;
    const int am = (tid & 255) >> 1, ak = (tid & 1) * 8;
    const int bj = (tid & 255) >> 2, bk = (tid & 3) * 4;
    const int r = m0 + am;
    const long abase = ((long)((r & 63) * 256 + (r >> 6))) * 1024;
    const long bbase = (long)(n0 + bj) * 1024;
    const bool ldr = tid < 256;

    const int wm = (warp >> 2) * 64, wn = (warp & 3) * 16;
    const int lr = lane >> 2, lc = lane & 3;

    float acc[4][2][4];
#pragma unroll
    for (int i = 0; i < 4; i++)
#pragma unroll
        for (int j = 0; j < 2; j++)
#pragma unroll
            for (int k = 0; k < 4; k++) acc[i][j][k] = 0.0f;

    const int NS = 64;
    if (ldr) {
        cp16(&As[0][am][ak],     dh + abase + ak);
        cp16(&As[0][am][ak + 4], dh + abase + ak + 4);
        cp16(&Bs[0][bj][bk],     U_attn + bbase + bk);
    }
    CP_COMMIT();

    for (int s = 0; s < NS; s++) {
        if (s + 1 < NS) {
            int buf = (s + 1) & 1, k0 = (s + 1) * 16;
            if (ldr) {
                cp16(&As[buf][am][ak],     dh + abase + k0 + ak);
                cp16(&As[buf][am][ak + 4], dh + abase + k0 + ak + 4);
                cp16(&Bs[buf][bj][bk],     U_attn + bbase + k0 + bk);
            }
            CP_COMMIT();
            CP_WAIT(1);
        } else {
            CP_WAIT(0);
        }
        __syncthreads();
        if (warp < 8) {
            const int buf = s & 1;
#pragma unroll
            for (int kk = 0; kk < 16; kk += 8) {
                uint32_t af[4][4], bf[2][2];
#pragma unroll
                for (int fm = 0; fm < 4; fm++) {
                    int rr = wm + fm * 16 + lr;
                    af[fm][0] = f2tf(As[buf][rr][kk + lc]);
                    af[fm][1] = f2tf(As[buf][rr + 8][kk + lc]);
                    af[fm][2] = f2tf(As[buf][rr][kk + lc + 4]);
                    af[fm][3] = f2tf(As[buf][rr + 8][kk + lc + 4]);
                }
#pragma unroll
                for (int fn = 0; fn < 2; fn++) {
                    int jc = wn + fn * 8 + lr;
                    bf[fn][0] = f2tf(Bs[buf][jc][kk + lc]);
                    bf[fn][1] = f2tf(Bs[buf][jc][kk + lc + 4]);
                }
#pragma unroll
                for (int fm = 0; fm < 4; fm++)
#pragma unroll
                    for (int fn = 0; fn < 2; fn++) mma8(acc[fm][fn], af[fm], bf[fn]);
            }
        }
        __syncthreads();
    }

    if (warp < 8) {
#pragma unroll
        for (int fm = 0; fm < 4; fm++) {
#pragma unroll
            for (int fn = 0; fn < 2; fn++) {
                int rr = m0 + wm + fm * 16 + lr;
                int a  = n0 + wn + fn * 8 + 2 * lc;
                float ba0 = b_attn[a], ba1 = b_attn[a + 1];
                float2 v0 = make_float2(acc[fm][fn][0] + ba0, acc[fm][fn][1] + ba1);
                float2 v1 = make_float2(acc[fm][fn][2] + ba0, acc[fm][fn][3] + ba1);
                *(float2*)&g_Uv[rr * ATTN + a]       = v0;
                *(float2*)&g_Uv[(rr + 8) * ATTN + a] = v1;
            }
        }
    }
}

// smem (bytes): A stages 8 x 16KB = 128KB ; B stages 8 x 8KB = 64KB
#define SM_A(sl)  ((sl) * 16384)
#define SM_B(sl)  (131072 + (sl) * 8192)
#define GK_SMEM_BYTES 196608

// ---------------- the persistent kernel ----------------
__global__ __launch_bounds__(NTHR, 1) void recon_kernel(
    const float* __restrict__ dh, const int* __restrict__ caps,
    const float* __restrict__ W_attn, const float* __restrict__ U_attn,
    const float* __restrict__ b_attn, const float* __restrict__ w_attn,
    const float* __restrict__ W_ih, const float* __restrict__ W_hh,
    const float* __restrict__ b_ih, const float* __restrict__ b_hh,
    float* __restrict__ out, int T_feat)
{
    extern __shared__ __align__(1024) float smem[];
    __shared__ float bias_s[64];

    const int tid = threadIdx.x, blk = blockIdx.x;
    const int warp = tid >> 5, lane = tid & 31;
    int sense = 0;

    const int gm0 = (blk & 1) * 128;
    const int gn0 = (blk >> 1) * 16;

    char* smem_c = (char*)smem;
    const uint32_t smem_base = smem_u32(smem);

    if (tid < 64) {
        int row = (tid & 3) * 1024 + gn0 + (tid >> 2);
        bias_s[tid] = b_ih[row] + b_hh[row];
    }

    // ---- phase 0 ----
    for (int i = blk * NTHR + tid; i < BATCH * HID; i += NBLK * NTHR) {
        g_h[0][i]   = 0.0f;
        g_h_h[0][i] = __float2half_rn(0.0f);
        g_c[i]      = 0.0f;
    }
    for (int i = blk * NTHR + tid; i < 4 * HID * DEC; i += NBLK * NTHR)
        g_Wih_h[i] = __float2half_rn(W_ih[i]);
    for (int i = blk * NTHR + tid; i < 4 * HID * HID; i += NBLK * NTHR)
        g_Whh_h[i] = __float2half_rn(W_hh[i]);
    for (int tix = blk; tix < 256; tix += NBLK)
        uv_tile(smem, dh, U_attn, b_attn, (tix & 127) * 128, (tix >> 7) * 64);
    gsync(&sense);

    // ---- gates loaders: A 128 rows x 64k fp16 (16KB), B 64 j x 64k fp16 (8KB) ----
    const int a_row = tid >> 2;
    const int a_c   = (tid & 3) * 16;
    const long a_goff = (long)(gm0 + a_row) * 1024 + a_c;
    const int a_so  = a_row * 128 + a_c * 2;
    const int b_row = tid >> 3;
    const int b_c   = (tid & 7) * 8;
    const long b_goff = (long)((b_row & 3) * 1024 + gn0 + (b_row >> 2)) * 1024 + b_c;
    const int b_so  = b_row * 128 + b_c * 2;

    // ---- k-split groups: 2 groups x 8 warps; warp tile 32m x 32j (4m x 2j grid) ----
    const int grp = warp >> 3;          // 0: even stages, 1: odd stages
    const int wg  = warp & 7;
    const int wm  = (wg & 3) * 32;
    const int wn  = (wg >> 2) * 32;
    const int ls_row = ((lane >> 3) & 1) * 8 + (lane & 7);
    const int ls_colb = (lane >> 4) * 16;
    const uint32_t a_swz = SWZ((uint32_t)((wm + ls_row) * 128 + ls_colb));
    const uint32_t b_swz = SWZ((uint32_t)((wn + ls_row) * 128 + ls_colb));
    const int lr = lane >> 2, lc = lane & 3;

    for (int s = 0; s < T_feat; s++) {
        const float*  hprev   = g_h[s & 1];
        const __half* hprev_h = g_h_h[s & 1];
        float*  hnext   = g_h[(s + 1) & 1];
        __half* hnext_h = g_h_h[(s + 1) & 1];

        // ================= attention: 2 batch rows per block =================
        {
            const int b0 = blk * 2;
            float* hs  = smem;           // [2][1024]
            float* whs = smem + 2048;    // [2][128]
            float* wa  = smem + 2304;    // [128]
            float* es  = smem + 2432;    // [2][64]
            float* ps  = smem + 2560;    // [2][64]

            for (int i = tid; i < 2 * HID; i += NTHR)
                hs[i] = __ldcg(&hprev[b0 * HID + i]);
            if (tid < ATTN) wa[tid] = w_attn[tid];
            __syncthreads();

            const float4* h0v = (const float4*)hs;
            const float4* h1v = (const float4*)(hs + 1024);
#pragma unroll
            for (int rr = 0; rr < 8; rr++) {
                int a = warp * 8 + rr;
                const float4* wrow = (const float4*)(W_attn + a * 1024);
                float d0 = 0.f, d1 = 0.f;
#pragma unroll
                for (int j = 0; j < 8; j++) {
                    float4 w4 = wrow[lane + 32 * j];
                    float4 x4 = h0v[lane + 32 * j];
                    float4 y4 = h1v[lane + 32 * j];
                    d0 += w4.x * x4.x + w4.y * x4.y + w4.z * x4.z + w4.w * x4.w;
                    d1 += w4.x * y4.x + w4.y * y4.y + w4.z * y4.z + w4.w * y4.w;
                }
#pragma unroll
                for (int off = 16; off; off >>= 1) {
                    d0 += __shfl_xor_sync(0xffffffffu, d0, off);
                    d1 += __shfl_xor_sync(0xffffffffu, d1, off);
                }
                if (lane == 0) { whs[a] = d0; whs[128 + a] = d1; }
            }
            __syncthreads();

            for (int t = warp; t < T_CAP; t += 16) {
#pragma unroll
                for (int bi = 0; bi < 2; bi++) {
                    const float* uv = g_Uv + ((long)(b0 + bi) * T_CAP + t) * ATTN;
                    float sE = 0.f;
#pragma unroll
                    for (int q = 0; q < 4; q++) {
                        int a = lane + q * 32;
                        sE += wa[a] * tanh_fast(whs[bi * 128 + a] + uv[a]);
                    }
#pragma unroll
                    for (int off = 16; off; off >>= 1)
                        sE += __shfl_xor_sync(0xffffffffu, sE, off);
                    if (lane == 0) {
                        int cp = caps[t * BATCH + b0 + bi];
                        es[bi * 64 + t] = (cp != 0 && cp != 2) ? sE : -1e30f;
                    }
                }
            }
            __syncthreads();

            if (warp < 2) {
                int bi = warp;
                float e0 = es[bi * 64 + lane], e1 = es[bi * 64 + lane + 32];
                float mx = fmaxf(e0, e1);
#pragma unroll
                for (int off = 16; off; off >>= 1)
                    mx = fmaxf(mx, __shfl_xor_sync(0xffffffffu, mx, off));
                float x0 = __expf(e0 - mx), x1 = __expf(e1 - mx);
                float sm = x0 + x1;
#pragma unroll
                for (int off = 16; off; off >>= 1)
                    sm += __shfl_xor_sync(0xffffffffu, sm, off);
                float inv = 1.0f / sm;
                ps[bi * 64 + lane]      = x0 * inv;
                ps[bi * 64 + lane + 32] = x1 * inv;
            }
            __syncthreads();

            {
                const int row = tid >> 8;
                const int d = (tid & 255) * 4;
                float4 a0 = make_float4(0.f, 0.f, 0.f, 0.f);
                const float* pr = ps + row * 64;
#pragma unroll 4
                for (int t = 0; t < T_CAP; t++) {
                    float p = pr[t];
                    float4 x = *(const float4*)&dh[(long)(t * BATCH + b0 + row) * DEC + d];
                    a0.x += p * x.x; a0.y += p * x.y; a0.z += p * x.z; a0.w += p * x.w;
                }
                __half2 lo = __floats2half2_rn(a0.x, a0.y);
                __half2 hi = __floats2half2_rn(a0.z, a0.w);
                uint2 pk;
                pk.x = *(uint32_t*)&lo;
                pk.y = *(uint32_t*)&hi;
                *(uint2*)&g_ctx_h[(long)(b0 + row) * DEC + d] = pk;
            }
        }
        gsync(&sense);

        // ===== gates: 128m x 64j x 2048k fp16; 2 k-groups on alternating stages =====
        {
            const int NS = 32;   // BK=64 stages
            const int NP = 16;   // stage pairs

            auto load_stage = [&](int ks) {
                int sl = ks & 7;
                int k0 = ks * 64;
                int kb = k0 & 1023;
                const __half* Asrc = ((k0 < 1024) ? g_ctx_h : hprev_h) + a_goff + kb;
                const __half* Bsrc = ((k0 < 1024) ? g_Wih_h : g_Whh_h) + b_goff + kb;
                char* Ab = smem_c + SM_A(sl);
                char* Bb = smem_c + SM_B(sl);
                cp16cg(Ab + SWZ(a_so),      Asrc);
                cp16cg(Ab + SWZ(a_so + 16), Asrc + 8);
                cp16(Bb + SWZ(b_so), Bsrc);
                CP_COMMIT();
            };

            float acc[2][4][4];
#pragma unroll
            for (int i = 0; i < 2; i++)
#pragma unroll
                for (int j = 0; j < 4; j++)
#pragma unroll
                    for (int k = 0; k < 4; k++) acc[i][j][k] = 0.0f;

            // preload 4 stages (2 pairs)
#pragma unroll
            for (int p = 0; p < 4; p++) load_stage(p);

            for (int t = 0; t < NP; t++) {
                int f = 2 * t + 4;
                if (f < NS)     load_stage(f);
                if (f + 1 < NS) load_stage(f + 1);
                if (t <= NP - 3)      { CP_WAIT(4); }
                else if (t == NP - 2) { CP_WAIT(2); }
                else                  { CP_WAIT(0); }
                __syncthreads();

                const int sl = (2 * t + grp) & 7;
                const uint32_t Ab = smem_base + SM_A(sl);
                const uint32_t Bb = smem_base + SM_B(sl);
#pragma unroll
                for (int kk = 0; kk < 4; kk++) {
                    const uint32_t kofs = (uint32_t)(kk * 32);
                    uint32_t af0[4], af1[4], bfa[4], bfb[4];
                    ldsm4(af0, Ab + (a_swz ^ kofs));
                    ldsm4(af1, Ab + 2048 + (a_swz ^ kofs));
                    ldsm4(bfa, Bb + (b_swz ^ kofs));
                    ldsm4(bfb, Bb + 2048 + (b_swz ^ kofs));
                    uint32_t b0[2] = {bfa[0], bfa[2]};
                    uint32_t b1[2] = {bfa[1], bfa[3]};
                    uint32_t b2[2] = {bfb[0], bfb[2]};
                    uint32_t b3[2] = {bfb[1], bfb[3]};
                    mma16(acc[0][0], af0, b0);
                    mma16(acc[0][1], af0, b1);
                    mma16(acc[0][2], af0, b2);
                    mma16(acc[0][3], af0, b3);
                    mma16(acc[1][0], af1, b0);
                    mma16(acc[1][1], af1, b1);
                    mma16(acc[1][2], af1, b2);
                    mma16(acc[1][3], af1, b3);
                }
            }

            __syncthreads();  // stage smem dead; overlay gates tile

            float (*gs)[68] = (float(*)[68])smem;
            if (grp == 0) {
#pragma unroll
                for (int fm = 0; fm < 2; fm++) {
#pragma unroll
                    for (int fn = 0; fn < 4; fn++) {
                        int m = wm + fm * 16 + lr;
                        int j = wn + fn * 8 + 2 * lc;
                        *(float2*)&gs[m][j]     = make_float2(acc[fm][fn][0], acc[fm][fn][1]);
                        *(float2*)&gs[m + 8][j] = make_float2(acc[fm][fn][2], acc[fm][fn][3]);
                    }
                }
            }
            __syncthreads();
            if (grp == 1) {
#pragma unroll
                for (int fm = 0; fm < 2; fm++) {
#pragma unroll
                    for (int fn = 0; fn < 4; fn++) {
                        int m = wm + fm * 16 + lr;
                        int j = wn + fn * 8 + 2 * lc;
                        float2 u0 = *(float2*)&gs[m][j];
                        float2 u1 = *(float2*)&gs[m + 8][j];
                        u0.x += acc[fm][fn][0]; u0.y += acc[fm][fn][1];
                        u1.x += acc[fm][fn][2]; u1.y += acc[fm][fn][3];
                        *(float2*)&gs[m][j]     = u0;
                        *(float2*)&gs[m + 8][j] = u1;
                    }
                }
            }
            __syncthreads();

            for (int q = tid; q < 128 * 16; q += NTHR) {
                int ml = q & 127, nl = q >> 7;
                float4 g4 = *(float4*)&gs[ml][nl * 4];
                float iv = g4.x + bias_s[nl * 4 + 0];
                float fv = g4.y + bias_s[nl * 4 + 1];
                float gv = g4.z + bias_s[nl * 4 + 2];
                float ov = g4.w + bias_s[nl * 4 + 3];
                int b = gm0 + ml, n = gn0 + nl;
                int idx = b * HID + n;
                float cold = g_c[idx];
                float cn = sigf(fv) * cold + sigf(iv) * tanhf(gv);
                float hn = sigf(ov) * tanhf(cn);
                g_c[idx] = cn;
                hnext[idx]   = hn;
                hnext_h[idx] = __float2half_rn(hn);
                out[(long)(b * T_feat + s) * HID + n] = hn;
            }
        }
        gsync(&sense);
    }

    gsync(&sense);  // total barriers even -> g_flag restored to 0
}

// ---------------- launcher ----------------
extern "C" void kernel_launch(void* const* d_in, const int* in_sizes, int n_in,
                              void* d_out, int out_size)
{
    int base = 2;
    if (n_in >= 11 && in_sizes[2] == 1) base = 3;

    const float* dh     = (const float*)d_in[0];
    const int*   caps   = (const int*)d_in[1];
    const float* W_attn = (const float*)d_in[base + 0];
    const float* U_attn = (const float*)d_in[base + 1];
    const float* b_attn = (const float*)d_in[base + 2];
    const float* w_attn = (const float*)d_in[base + 3];
    const float* W_ih   = (const float*)d_in[base + 4];
    const float* W_hh   = (const float*)d_in[base + 5];
    const float* b_ih   = (const float*)d_in[base + 6];
    const float* b_hh   = (const float*)d_in[base + 7];
    float* out = (float*)d_out;

    const int T_feat = out_size / (BATCH * HID);  // 28

    static int configured = 0;
    if (!configured) {
        cudaFuncSetAttribute(recon_kernel, cudaFuncAttributeMaxDynamicSharedMemorySize,
                             GK_SMEM_BYTES);
        configured = 1;
    }

    recon_kernel<<<NBLK, NTHR, GK_SMEM_BYTES>>>(
        dh, caps, W_attn, U_attn, b_attn, w_attn,
        W_ih, W_hh, b_ih, b_hh, out, T_feat);
}